// round 8
// baseline (speedup 1.0000x reference)
#include <cuda_runtime.h>
#include <cuda_bf16.h>
#include <math.h>
#include <stdint.h>
#include <stddef.h>

#define BB   128
#define NN   197
#define CC   768
#define HH   12
#define HD   64
#define OUTC 32
#define CHH  14
#define CHD  14
#define CNN  196
#define MLPH 3072
#define CMLPH 128
#define MROWS (BB*NN)          // 25216
#define CMROWS (BB*OUTC)       // 4096
#define NBH   (BB*HH)          // 1536

// ---------------- scratch ----------------
__device__ float g_qkv [MROWS*3*CC];
__device__ float g_attn[(size_t)NBH*NN*NN];
__device__ float g_x   [MROWS*CC];
__device__ float g_x32 [MROWS*OUTC];
__device__ float g_ln32[MROWS*OUTC];
__device__ float g_t   [BB*OUTC*CNN];
__device__ float g_cqkv[BB*OUTC*3*CNN];
__device__ float g_co  [BB*OUTC*CNN];
__device__ float g_co2 [BB*OUTC*CNN];
__device__ float g_cmlp[MROWS*CMLPH];
__device__ __nv_bfloat16 g_abf [(size_t)MROWS*2*CC];    // [hi|lo] activations
__device__ __nv_bfloat16 g_abf2[(size_t)MROWS*2*MLPH];  // [hi|lo] mlp hidden
__device__ __nv_bfloat16 g_wbf [(size_t)MLPH*2*CC];     // [hi|lo] weights
__device__ __nv_bfloat16 g_qs  [(size_t)NBH*4*3*4096];
__device__ __nv_bfloat16 g_ks  [(size_t)NBH*4*3*4096];
__device__ __nv_bfloat16 g_vt  [(size_t)NBH*4*3*4096];

__device__ __forceinline__ float gelu_f(float x) {
    return 0.5f * x * (1.0f + erff(x * 0.70710678118654752440f));
}

// ================= PTX helpers =================
__device__ __forceinline__ uint32_t smem_u32(const void* p) {
    uint32_t a;
    asm("{ .reg .u64 t; cvta.to.shared.u64 t, %1; cvt.u32.u64 %0, t; }" : "=r"(a) : "l"(p));
    return a;
}
#define CP_ASYNC16(d, s)    asm volatile("cp.async.cg.shared.global [%0], [%1], 16;" :: "r"(d), "l"(s))
#define CP_COMMIT()         asm volatile("cp.async.commit_group;" ::: "memory")
#define CP_WAIT1()          asm volatile("cp.async.wait_group 1;" ::: "memory")
#define CP_WAIT0()          asm volatile("cp.async.wait_group 0;" ::: "memory")

__device__ __forceinline__ void ldm_x4(uint32_t* r, uint32_t addr) {
    asm volatile("ldmatrix.sync.aligned.m8n8.x4.shared.b16 {%0,%1,%2,%3}, [%4];"
        : "=r"(r[0]), "=r"(r[1]), "=r"(r[2]), "=r"(r[3]) : "r"(addr));
}
__device__ __forceinline__ void mma_bf16(float* c, const uint32_t* a, const uint32_t* b) {
    asm volatile("mma.sync.aligned.m16n8k16.row.col.f32.bf16.bf16.f32 "
        "{%0,%1,%2,%3}, {%4,%5,%6,%7}, {%8,%9}, {%0,%1,%2,%3};"
        : "+f"(c[0]), "+f"(c[1]), "+f"(c[2]), "+f"(c[3])
        : "r"(a[0]), "r"(a[1]), "r"(a[2]), "r"(a[3]), "r"(b[0]), "r"(b[1]));
}
__device__ __forceinline__ uint32_t swz(uint32_t off) { return off ^ ((off >> 3) & 0x70); }
__device__ __forceinline__ void split2(float a, float b, __nv_bfloat162& hp, __nv_bfloat162& lp) {
    __nv_bfloat16 h0 = __float2bfloat16(a), h1 = __float2bfloat16(b);
    hp = __nv_bfloat162(h0, h1);
    lp = __nv_bfloat162(__float2bfloat16(a - __bfloat162float(h0)),
                        __float2bfloat16(b - __bfloat162float(h1)));
}

// ================= conversions =================
// [hi K | lo K] rows, for activations and weights alike
__global__ void conv_x2(const float* __restrict__ in, __nv_bfloat16* __restrict__ out,
                        int Mr, int K) {
    long long idx = (long long)blockIdx.x * 256 + threadIdx.x;
    long long tot = (long long)Mr * (K / 4);
    if (idx >= tot) return;
    int m = (int)(idx / (K / 4)), k = (int)(idx % (K / 4)) * 4;
    float4 v = *(const float4*)(in + (size_t)m * K + k);
    __nv_bfloat162 hp0, lp0, hp1, lp1;
    split2(v.x, v.y, hp0, lp0); split2(v.z, v.w, hp1, lp1);
    __nv_bfloat16* row = out + (size_t)m * 2 * K;
    *(__nv_bfloat162*)(row + k) = hp0;           *(__nv_bfloat162*)(row + k + 2) = hp1;
    *(__nv_bfloat162*)(row + K + k) = lp0;       *(__nv_bfloat162*)(row + K + k + 2) = lp1;
}
__global__ void conv_qk(const float* __restrict__ qkv, __nv_bfloat16* __restrict__ Qs,
                        __nv_bfloat16* __restrict__ Ks) {
    int idx = blockIdx.x * 256 + threadIdx.x;
    if (idx >= NBH * 197 * 32) return;
    int d2 = (idx & 31) * 2;
    int n  = (idx >> 5) % 197;
    int bh = idx / (32 * 197);
    int b = bh / HH, h = bh % HH;
    const float* src = qkv + (size_t)(b * NN + n) * (3 * CC) + h * HD + d2;
    float2 q = *(const float2*)src;
    float2 k = *(const float2*)(src + CC);
    __nv_bfloat162 qh, ql, kh, kl;
    split2(q.x, q.y, qh, ql); split2(k.x, k.y, kh, kl);
    int qt = n >> 6, r = n & 63;
    size_t base = ((size_t)(bh * 4 + qt) * 3) * 4096 + r * 64 + d2;
    *(__nv_bfloat162*)(Qs + base)        = qh;
    *(__nv_bfloat162*)(Qs + base + 4096) = qh;
    *(__nv_bfloat162*)(Qs + base + 8192) = ql;
    *(__nv_bfloat162*)(Ks + base)        = kh;
    *(__nv_bfloat162*)(Ks + base + 4096) = kl;
    *(__nv_bfloat162*)(Ks + base + 8192) = kh;
}
__global__ void conv_vt(const float* __restrict__ qkv, __nv_bfloat16* __restrict__ Vt) {
    int ct = blockIdx.x;
    int bh = ct >> 2, kt = ct & 3;
    int b = bh / HH, h = bh % HH;
    __shared__ float t[64][65];
    int tid = threadIdx.x;
    for (int i = tid; i < 4096; i += 256) {
        int kk = i >> 6, d = i & 63;
        int k = kt * 64 + kk;
        t[kk][d] = (k < NN) ? qkv[(size_t)(b * NN + k) * (3 * CC) + 2 * CC + h * HD + d] : 0.f;
    }
    __syncthreads();
    __nv_bfloat16* dst = Vt + ((size_t)ct * 3) * 4096;
    for (int i = tid; i < 2048; i += 256) {
        int d = i >> 5, kk2 = (i & 31) << 1;
        __nv_bfloat162 hp, lp;
        split2(t[kk2][d], t[kk2 + 1][d], hp, lp);
        size_t base = (size_t)d * 64 + kk2;
        *(__nv_bfloat162*)(dst + base)        = hp;
        *(__nv_bfloat162*)(dst + base + 4096) = lp;
        *(__nv_bfloat162*)(dst + base + 8192) = hp;
    }
}

// ================= mma.sync bf16 NT GEMM, 2-slab storage, 3-pass chunks =================
// A[M][2K] = [hi|lo], Bw[N][2K] = [hi|lo].  C = A_hi*W_hi + A_hi*W_lo + A_lo*W_hi.
// Chunk = 32 original-K; smem row 128B = [hi 64B | lo 64B], SW128 swizzle.
template<int BN, bool GELU, bool RES, bool X2>
__global__ void __launch_bounds__(256, 2)
gemm_mma(const __nv_bfloat16* __restrict__ A, const __nv_bfloat16* __restrict__ Bw,
         const float* __restrict__ bias, const float* __restrict__ res,
         float* __restrict__ C, __nv_bfloat16* __restrict__ Cx2, int M, int N, int K) {
    constexpr int A_BYTES = 128 * 128;
    constexpr int B_BYTES = BN * 128;
    constexpr int STAGE = A_BYTES + B_BYTES;
    constexpr int NSTG = 3;
    constexpr int WN = BN / 2;
    constexpr int MF = 2;
    constexpr int NF = WN / 8;

    extern __shared__ char smraw[];
    char* sm = (char*)(((uintptr_t)smraw + 1023) & ~(uintptr_t)1023);
    uint32_t smb = smem_u32(sm);

    int tid = threadIdx.x, wid = tid >> 5, lane = tid & 31;
    int wm = wid & 3, wn = wid >> 2;
    int bm = blockIdx.y * 128, bn = blockIdx.x * BN;
    const __nv_bfloat16* Ab = A + (size_t)bm * 2 * K;
    const __nv_bfloat16* Bb = Bw + (size_t)bn * 2 * K;
    const int nch = K >> 5;   // 32-K chunks

    auto load_chunk = [&](int c, int s) {
        int k0 = c << 5;
        uint32_t sa = smb + s * STAGE;
        #pragma unroll
        for (int i = 0; i < (128 * 8) / 256; i++) {
            int idx = tid + i * 256;
            int r = idx >> 3, u = idx & 7;
            const __nv_bfloat16* src = Ab + (size_t)r * 2 * K +
                ((u < 4) ? (k0 + u * 8) : (K + k0 + (u - 4) * 8));
            CP_ASYNC16(sa + swz((r << 7) | (u << 4)), (const char*)src);
        }
        uint32_t sb = sa + A_BYTES;
        #pragma unroll
        for (int i = 0; i < (BN * 8 + 255) / 256; i++) {
            int idx = tid + i * 256;
            if (BN * 8 % 256 == 0 || idx < BN * 8) {
                int r = idx >> 3, u = idx & 7;
                const __nv_bfloat16* src = Bb + (size_t)r * 2 * K +
                    ((u < 4) ? (k0 + u * 8) : (K + k0 + (u - 4) * 8));
                CP_ASYNC16(sb + swz((r << 7) | (u << 4)), (const char*)src);
            }
        }
    };

    float acc[MF][NF][4];
    #pragma unroll
    for (int i = 0; i < MF; i++)
        #pragma unroll
        for (int j = 0; j < NF; j++)
            #pragma unroll
            for (int e = 0; e < 4; e++) acc[i][j][e] = 0.0f;

    load_chunk(0, 0); CP_COMMIT();
    if (nch > 1) load_chunk(1, 1);
    CP_COMMIT();

    int a_mi = lane >> 3, a_r = lane & 7;
    int b_grp = lane >> 3, b_r = lane & 7;

    for (int c = 0; c < nch; c++) {
        CP_WAIT1();
        __syncthreads();
        if (c + 2 < nch) load_chunk(c + 2, (c + 2) % NSTG);
        CP_COMMIT();

        int s = c % NSTG;
        uint32_t sa = smb + s * STAGE;
        uint32_t sb = sa + A_BYTES;
        #pragma unroll
        for (int ks = 0; ks < 2; ks++) {
            // A_hi fragments (units 0-3)
            uint32_t afh[MF][4];
            #pragma unroll
            for (int mf = 0; mf < MF; mf++) {
                int row = wm * 32 + mf * 16 + ((a_mi & 1) << 3) + a_r;
                ldm_x4(afh[mf], sa + swz((row << 7) | ((ks * 2 + (a_mi >> 1)) << 4)));
            }
            // pass 1: A_hi * W_hi
            #pragma unroll
            for (int nfp = 0; nfp < NF / 2; nfp++) {
                uint32_t bfr[4];
                int row = wn * WN + (nfp * 2 + (b_grp >> 1)) * 8 + b_r;
                ldm_x4(bfr, sb + swz((row << 7) | ((ks * 2 + (b_grp & 1)) << 4)));
                #pragma unroll
                for (int mf = 0; mf < MF; mf++) {
                    mma_bf16(acc[mf][nfp * 2 + 0], afh[mf], bfr);
                    mma_bf16(acc[mf][nfp * 2 + 1], afh[mf], bfr + 2);
                }
            }
            // pass 2: A_hi * W_lo (units 4-7)
            #pragma unroll
            for (int nfp = 0; nfp < NF / 2; nfp++) {
                uint32_t bfr[4];
                int row = wn * WN + (nfp * 2 + (b_grp >> 1)) * 8 + b_r;
                ldm_x4(bfr, sb + swz((row << 7) | ((4 + ks * 2 + (b_grp & 1)) << 4)));
                #pragma unroll
                for (int mf = 0; mf < MF; mf++) {
                    mma_bf16(acc[mf][nfp * 2 + 0], afh[mf], bfr);
                    mma_bf16(acc[mf][nfp * 2 + 1], afh[mf], bfr + 2);
                }
            }
            // pass 3: A_lo * W_hi
            uint32_t afl[MF][4];
            #pragma unroll
            for (int mf = 0; mf < MF; mf++) {
                int row = wm * 32 + mf * 16 + ((a_mi & 1) << 3) + a_r;
                ldm_x4(afl[mf], sa + swz((row << 7) | ((4 + ks * 2 + (a_mi >> 1)) << 4)));
            }
            #pragma unroll
            for (int nfp = 0; nfp < NF / 2; nfp++) {
                uint32_t bfr[4];
                int row = wn * WN + (nfp * 2 + (b_grp >> 1)) * 8 + b_r;
                ldm_x4(bfr, sb + swz((row << 7) | ((ks * 2 + (b_grp & 1)) << 4)));
                #pragma unroll
                for (int mf = 0; mf < MF; mf++) {
                    mma_bf16(acc[mf][nfp * 2 + 0], afl[mf], bfr);
                    mma_bf16(acc[mf][nfp * 2 + 1], afl[mf], bfr + 2);
                }
            }
        }
    }

    int cr = lane >> 2, cc2 = (lane & 3) << 1;
    #pragma unroll
    for (int mf = 0; mf < MF; mf++) {
        #pragma unroll
        for (int half = 0; half < 2; half++) {
            int gm = bm + wm * 32 + mf * 16 + cr + half * 8;
            #pragma unroll
            for (int nf = 0; nf < NF; nf++) {
                int gn = bn + wn * WN + nf * 8 + cc2;
                float v0 = acc[mf][nf][half * 2 + 0];
                float v1 = acc[mf][nf][half * 2 + 1];
                if (bias) { v0 += __ldg(&bias[gn]); v1 += __ldg(&bias[gn + 1]); }
                if (GELU) { v0 = gelu_f(v0); v1 = gelu_f(v1); }
                if (X2) {
                    __nv_bfloat162 hp, lp;
                    split2(v0, v1, hp, lp);
                    __nv_bfloat16* row = Cx2 + (size_t)gm * (2 * N);
                    *(__nv_bfloat162*)(row + gn) = hp;
                    *(__nv_bfloat162*)(row + N + gn) = lp;
                } else {
                    if (RES) {
                        float2 rv = *(const float2*)(res + (size_t)gm * N + gn);
                        v0 += rv.x; v1 += rv.y;
                    }
                    *(float2*)(C + (size_t)gm * N + gn) = make_float2(v0, v1);
                }
            }
        }
    }
}

// ================= HMMA attention (unchanged, 3-slab) =================
__global__ void __launch_bounds__(128)
attn_qk_mma(const __nv_bfloat16* __restrict__ Qs, const __nv_bfloat16* __restrict__ Ks,
            float* __restrict__ S) {
    __shared__ __align__(128) char sm[49152];
    char* smp = sm;
    uint32_t smb = smem_u32(sm);
    int kt = blockIdx.x, qt = blockIdx.y, bh = blockIdx.z;
    int tid = threadIdx.x, wid = tid >> 5, lane = tid & 31;
    const char* Qb = (const char*)(Qs + ((size_t)(bh * 4 + qt) * 3) * 4096);
    const char* Kb = (const char*)(Ks + ((size_t)(bh * 4 + kt) * 3) * 4096);
    for (int c = tid; c < 1536; c += 128) {
        int slab = c >> 9, rem = c & 511, row = rem >> 3, unit = rem & 7;
        uint32_t off = slab * 8192 + swz((row << 7) | (unit << 4));
        CP_ASYNC16(smb + off, Qb + (size_t)c * 16);
        CP_ASYNC16(smb + 24576 + off, Kb + (size_t)c * 16);
    }
    CP_COMMIT(); CP_WAIT0();
    __syncthreads();
    (void)smp;

    float acc[8][4];
    #pragma unroll
    for (int i = 0; i < 8; i++)
        #pragma unroll
        for (int e = 0; e < 4; e++) acc[i][e] = 0.f;
    int a_mi = lane >> 3, a_r = lane & 7, b_grp = lane >> 3, b_r = lane & 7;
    uint32_t smQ = smb, smK = smb + 24576;
    #pragma unroll
    for (int slab = 0; slab < 3; slab++) {
        #pragma unroll
        for (int ks = 0; ks < 4; ks++) {
            uint32_t afr[4];
            int arow = wid * 16 + ((a_mi & 1) << 3) + a_r;
            ldm_x4(afr, smQ + slab * 8192 + swz((arow << 7) | ((ks * 2 + (a_mi >> 1)) << 4)));
            #pragma unroll
            for (int nfp = 0; nfp < 4; nfp++) {
                uint32_t bfr[4];
                int brow = (nfp * 2 + (b_grp >> 1)) * 8 + b_r;
                ldm_x4(bfr, smK + slab * 8192 + swz((brow << 7) | ((ks * 2 + (b_grp & 1)) << 4)));
                mma_bf16(acc[nfp * 2 + 0], afr, bfr);
                mma_bf16(acc[nfp * 2 + 1], afr, bfr + 2);
            }
        }
    }
    int cr = lane >> 2, cc2 = (lane & 3) << 1;
    #pragma unroll
    for (int nf = 0; nf < 8; nf++) {
        #pragma unroll
        for (int half = 0; half < 2; half++) {
            int q = qt * 64 + wid * 16 + cr + half * 8;
            int k = kt * 64 + nf * 8 + cc2;
            if (q < NN) {
                float* dst = S + ((size_t)bh * NN + q) * NN + k;
                if (k < NN)     dst[0] = acc[nf][half * 2 + 0] * 0.125f;
                if (k + 1 < NN) dst[1] = acc[nf][half * 2 + 1] * 0.125f;
            }
        }
    }
}

// O = P@V, writes [hi|lo] 2-slab rows into proj's A buffer
__global__ void __launch_bounds__(128)
attn_av_mma(const float* __restrict__ P, const __nv_bfloat16* __restrict__ Vt,
            __nv_bfloat16* __restrict__ Ox2) {
    __shared__ __align__(128) char sm[49152];
    char* smp = sm;
    uint32_t smb = smem_u32(sm);
    int qt = blockIdx.x, bh = blockIdx.y;
    int b = bh / HH, h = bh % HH;
    int tid = threadIdx.x, wid = tid >> 5, lane = tid & 31;
    float acc[8][4];
    #pragma unroll
    for (int i = 0; i < 8; i++)
        #pragma unroll
        for (int e = 0; e < 4; e++) acc[i][e] = 0.f;
    int a_mi = lane >> 3, a_r = lane & 7, b_grp = lane >> 3, b_r = lane & 7;
    uint32_t smP = smb, smV = smb + 24576;

    for (int kt = 0; kt < 4; kt++) {
        const char* Vb = (const char*)(Vt + ((size_t)(bh * 4 + kt) * 3) * 4096);
        for (int c = tid; c < 1536; c += 128) {
            int slab = c >> 9, rem = c & 511, row = rem >> 3, unit = rem & 7;
            CP_ASYNC16(smV + slab * 8192 + swz((row << 7) | (unit << 4)), Vb + (size_t)c * 16);
        }
        CP_COMMIT();
        #pragma unroll
        for (int i = 0; i < 8; i++) {
            int lin = i * 128 + tid;
            int q = lin >> 4, k4 = (lin & 15) << 2;
            int qg = qt * 64 + q, kg = kt * 64 + k4;
            float p[4];
            #pragma unroll
            for (int e = 0; e < 4; e++)
                p[e] = (qg < NN && kg + e < NN) ? P[((size_t)bh * NN + qg) * NN + kg + e] : 0.f;
            __nv_bfloat162 hp0, lp0, hp1, lp1;
            split2(p[0], p[1], hp0, lp0); split2(p[2], p[3], hp1, lp1);
            uint32_t off = swz((q << 7) | (k4 << 1));
            *(__nv_bfloat162*)(smp + off)             = hp0;
            *(__nv_bfloat162*)(smp + off + 4)         = hp1;
            *(__nv_bfloat162*)(smp + 8192 + off)      = hp0;
            *(__nv_bfloat162*)(smp + 8192 + off + 4)  = hp1;
            *(__nv_bfloat162*)(smp + 16384 + off)     = lp0;
            *(__nv_bfloat162*)(smp + 16384 + off + 4) = lp1;
        }
        CP_WAIT0();
        __syncthreads();
        #pragma unroll
        for (int slab = 0; slab < 3; slab++) {
            #pragma unroll
            for (int ks = 0; ks < 4; ks++) {
                uint32_t afr[4];
                int arow = wid * 16 + ((a_mi & 1) << 3) + a_r;
                ldm_x4(afr, smP + slab * 8192 + swz((arow << 7) | ((ks * 2 + (a_mi >> 1)) << 4)));
                #pragma unroll
                for (int nfp = 0; nfp < 4; nfp++) {
                    uint32_t bfr[4];
                    int brow = (nfp * 2 + (b_grp >> 1)) * 8 + b_r;
                    ldm_x4(bfr, smV + slab * 8192 + swz((brow << 7) | ((ks * 2 + (b_grp & 1)) << 4)));
                    mma_bf16(acc[nfp * 2 + 0], afr, bfr);
                    mma_bf16(acc[nfp * 2 + 1], afr, bfr + 2);
                }
            }
        }
        __syncthreads();
    }
    int cr = lane >> 2, cc2 = (lane & 3) << 1;
    #pragma unroll
    for (int nf = 0; nf < 8; nf++) {
        #pragma unroll
        for (int half = 0; half < 2; half++) {
            int q = qt * 64 + wid * 16 + cr + half * 8;
            if (q < NN) {
                int m = b * NN + q;
                int col = h * HD + nf * 8 + cc2;
                __nv_bfloat162 hp, lp;
                split2(acc[nf][half * 2 + 0], acc[nf][half * 2 + 1], hp, lp);
                __nv_bfloat16* row = Ox2 + (size_t)m * (2 * CC);
                *(__nv_bfloat162*)(row + col) = hp;
                *(__nv_bfloat162*)(row + CC + col) = lp;
            }
        }
    }
}

// ---------------- LayerNorm D=768 -> [hi|lo] ----------------
__global__ void ln768_x2(const float* __restrict__ x, const float* __restrict__ g,
                         const float* __restrict__ b, __nv_bfloat16* __restrict__ out) {
    int row = blockIdx.x;
    const float* p = x + (size_t)row * CC;
    int tid = threadIdx.x;
    float v0 = p[tid], v1 = p[tid + 256], v2 = p[tid + 512];
    float s = v0 + v1 + v2;
    float sq = v0 * v0 + v1 * v1 + v2 * v2;
    __shared__ float rs[256], rq[256];
    rs[tid] = s; rq[tid] = sq; __syncthreads();
    for (int st = 128; st > 0; st >>= 1) {
        if (tid < st) { rs[tid] += rs[tid + st]; rq[tid] += rq[tid + st]; }
        __syncthreads();
    }
    float mean = rs[0] * (1.0f / CC);
    float var  = rq[0] * (1.0f / CC) - mean * mean;
    float inv = rsqrtf(var + 1e-5f);
    __nv_bfloat16* o = out + (size_t)row * (2 * CC);
    #pragma unroll
    for (int j = 0; j < 3; j++) {
        int c = tid + j * 256;
        float y = (p[c] - mean) * inv * g[c] + b[c];
        __nv_bfloat16 hi = __float2bfloat16(y);
        o[c] = hi;
        o[CC + c] = __float2bfloat16(y - __bfloat162float(hi));
    }
}

// ---------------- LayerNorm D=32 ----------------
__global__ void ln32_kernel(const float* __restrict__ x, const float* __restrict__ g,
                            const float* __restrict__ b, float* __restrict__ out) {
    int row = blockIdx.x * 8 + threadIdx.x / 32;
    int lane = threadIdx.x & 31;
    float v = x[(size_t)row * OUTC + lane];
    float s = v, sq = v * v;
    #pragma unroll
    for (int o = 16; o > 0; o >>= 1) {
        s  += __shfl_xor_sync(0xffffffff, s, o);
        sq += __shfl_xor_sync(0xffffffff, sq, o);
    }
    float mean = s * (1.0f / OUTC);
    float var  = sq * (1.0f / OUTC) - mean * mean;
    float inv = rsqrtf(var + 1e-5f);
    out[(size_t)row * OUTC + lane] = (v - mean) * inv * g[lane] + b[lane];
}

// ---------------- fp32 SIMT GEMM (small channel GEMMs) ----------------
template<int BM, int BN, int BK, int TM, int TN, bool GELU, bool RES>
__global__ void gemm_nt(const float* __restrict__ A, const float* __restrict__ Bw,
                        const float* __restrict__ bias, const float* __restrict__ res,
                        float* __restrict__ C, int M, int N, int K) {
    constexpr int THREADS = (BM / TM) * (BN / TN);
    __shared__ float As[BK][BM];
    __shared__ float Bs[BK][BN];
    int tid = threadIdx.x;
    int bm = blockIdx.y * BM, bn = blockIdx.x * BN;
    int tx = tid % (BN / TN), ty = tid / (BN / TN);
    float acc[TM][TN];
    #pragma unroll
    for (int i = 0; i < TM; i++)
        #pragma unroll
        for (int j = 0; j < TN; j++) acc[i][j] = 0.0f;
    constexpr int A4 = BM * BK / 4;
    constexpr int B4 = BN * BK / 4;
    for (int k0 = 0; k0 < K; k0 += BK) {
        #pragma unroll
        for (int i = tid; i < A4; i += THREADS) {
            int row = i / (BK / 4);
            int kk  = (i % (BK / 4)) * 4;
            float4 v = make_float4(0.f, 0.f, 0.f, 0.f);
            if (k0 + kk < K) v = *(const float4*)(A + (size_t)(bm + row) * K + k0 + kk);
            As[kk + 0][row] = v.x; As[kk + 1][row] = v.y;
            As[kk + 2][row] = v.z; As[kk + 3][row] = v.w;
        }
        #pragma unroll
        for (int i = tid; i < B4; i += THREADS) {
            int row = i / (BK / 4);
            int kk  = (i % (BK / 4)) * 4;
            float4 v = make_float4(0.f, 0.f, 0.f, 0.f);
            if (bn + row < N && k0 + kk < K)
                v = *(const float4*)(Bw + (size_t)(bn + row) * K + k0 + kk);
            Bs[kk + 0][row] = v.x; Bs[kk + 1][row] = v.y;
            Bs[kk + 2][row] = v.z; Bs[kk + 3][row] = v.w;
        }
        __syncthreads();
        #pragma unroll
        for (int kk = 0; kk < BK; kk++) {
            float a[TM], bv[TN];
            #pragma unroll
            for (int i = 0; i < TM; i++) a[i] = As[kk][ty * TM + i];
            #pragma unroll
            for (int j = 0; j < TN; j++) bv[j] = Bs[kk][tx * TN + j];
            #pragma unroll
            for (int i = 0; i < TM; i++)
                #pragma unroll
                for (int j = 0; j < TN; j++) acc[i][j] += a[i] * bv[j];
        }
        __syncthreads();
    }
    #pragma unroll
    for (int i = 0; i < TM; i++) {
        int gm = bm + ty * TM + i;
        #pragma unroll
        for (int j = 0; j < TN; j++) {
            int gn = bn + tx * TN + j;
            if (gn < N) {
                float v = acc[i][j];
                if (bias) v += bias[gn];
                if (GELU) v = gelu_f(v);
                if (RES) v += res[(size_t)gm * N + gn];
                C[(size_t)gm * N + gn] = v;
            }
        }
    }
}

// ---------------- warp-per-row softmax over 197 ----------------
__global__ void softmax197_warp(float* __restrict__ S) {
    int row = blockIdx.x * 8 + (threadIdx.x >> 5);
    int lane = threadIdx.x & 31;
    float* p = S + (size_t)row * NN;
    float v[7];
    float mx = -INFINITY;
    #pragma unroll
    for (int j = 0; j < 7; j++) {
        int idx = lane + 32 * j;
        v[j] = (idx < NN) ? p[idx] : -INFINITY;
        mx = fmaxf(mx, v[j]);
    }
    #pragma unroll
    for (int o = 16; o > 0; o >>= 1) mx = fmaxf(mx, __shfl_xor_sync(0xffffffff, mx, o));
    float sum = 0.0f;
    #pragma unroll
    for (int j = 0; j < 7; j++) { v[j] = __expf(v[j] - mx); sum += (lane + 32 * j < NN) ? v[j] : 0.0f; }
    #pragma unroll
    for (int o = 16; o > 0; o >>= 1) sum += __shfl_xor_sync(0xffffffff, sum, o);
    float inv = 1.0f / sum;
    #pragma unroll
    for (int j = 0; j < 7; j++) {
        int idx = lane + 32 * j;
        if (idx < NN) p[idx] = v[j] * inv;
    }
}

// ---------------- t[b,c,s] = ln3[b, 1+s, c] ----------------
__global__ void make_t_kernel(const float* __restrict__ ln3, float* __restrict__ t) {
    int idx = blockIdx.x * 256 + threadIdx.x;
    if (idx >= BB * OUTC * CNN) return;
    int s = idx % CNN;
    int c = (idx / CNN) % OUTC;
    int b = idx / (CNN * OUTC);
    t[idx] = ln3[((size_t)(b * NN + 1 + s)) * OUTC + c];
}

// ---------------- tiny channel attention ----------------
__global__ void chattn_kernel(const float* __restrict__ cqkv, float* __restrict__ co) {
    int b = blockIdx.x / CHH, h = blockIdx.x % CHH;
    int tid = threadIdx.x;
    __shared__ float Q[OUTC][CHD], Kk[OUTC][CHD], V[OUTC][CHD], S[OUTC][OUTC + 1];
    const float* base = cqkv + (size_t)b * OUTC * (3 * CNN);
    for (int i = tid; i < OUTC * CHD; i += 256) {
        int r = i / CHD, d = i % CHD;
        Q[r][d]  = base[r * (3 * CNN) + h * CHD + d];
        Kk[r][d] = base[r * (3 * CNN) + CNN + h * CHD + d];
        V[r][d]  = base[r * (3 * CNN) + 2 * CNN + h * CHD + d];
    }
    __syncthreads();
    const float sc = rsqrtf((float)CHD);
    for (int i = tid; i < OUTC * OUTC; i += 256) {
        int qi = i / OUTC, kj = i % OUTC;
        float s = 0.0f;
        #pragma unroll
        for (int d = 0; d < CHD; d++) s += Q[qi][d] * Kk[kj][d];
        S[qi][kj] = s * sc;
    }
    __syncthreads();
    if (tid < OUTC) {
        float mx = -INFINITY;
        #pragma unroll
        for (int j = 0; j < OUTC; j++) mx = fmaxf(mx, S[tid][j]);
        float sum = 0.0f;
        #pragma unroll
        for (int j = 0; j < OUTC; j++) { float e = __expf(S[tid][j] - mx); S[tid][j] = e; sum += e; }
        float inv = 1.0f / sum;
        #pragma unroll
        for (int j = 0; j < OUTC; j++) S[tid][j] *= inv;
    }
    __syncthreads();
    for (int i = tid; i < OUTC * CHD; i += 256) {
        int qi = i / CHD, d = i % CHD;
        float s = 0.0f;
        #pragma unroll
        for (int kk = 0; kk < OUTC; kk++) s += S[qi][kk] * V[kk][d];
        co[((size_t)(b * OUTC + qi)) * CNN + h * CHD + d] = s;
    }
}

// ---------------- x32 += concat([ln3 cls, co2^T]) ----------------
__global__ void concat_add_kernel(const float* __restrict__ ln3, const float* __restrict__ co2,
                                  float* __restrict__ x32) {
    int idx = blockIdx.x * 256 + threadIdx.x;
    if (idx >= MROWS * OUTC) return;
    int c = idx % OUTC;
    int n = (idx / OUTC) % NN;
    int b = idx / (OUTC * NN);
    float add;
    if (n == 0) add = ln3[((size_t)b * NN) * OUTC + c];
    else        add = co2[((size_t)(b * OUTC + c)) * CNN + (n - 1)];
    x32[idx] += add;
}

// ---------------- launch ----------------
static inline int cdiv(long long a, int b) { return (int)((a + b - 1) / b); }

extern "C" void kernel_launch(void* const* d_in, const int* in_sizes, int n_in,
                              void* d_out, int out_size) {
    const float* x      = (const float*)d_in[0];
    const float* g1     = (const float*)d_in[1];
    const float* b1     = (const float*)d_in[2];
    const float* w_qkv  = (const float*)d_in[3];
    const float* w_proj = (const float*)d_in[4];
    const float* b_proj = (const float*)d_in[5];
    const float* g2     = (const float*)d_in[6];
    const float* b2     = (const float*)d_in[7];
    const float* w_fc1  = (const float*)d_in[8];
    const float* b_fc1  = (const float*)d_in[9];
    const float* w_fc2  = (const float*)d_in[10];
    const float* b_fc2  = (const float*)d_in[11];
    const float* g3     = (const float*)d_in[12];
    const float* b3     = (const float*)d_in[13];
    const float* w_cqkv = (const float*)d_in[14];
    const float* w_cproj= (const float*)d_in[15];
    const float* b_cproj= (const float*)d_in[16];
    const float* g4     = (const float*)d_in[17];
    const float* b4     = (const float*)d_in[18];
    const float* w_cfc1 = (const float*)d_in[19];
    const float* b_cfc1 = (const float*)d_in[20];
    const float* w_cfc2 = (const float*)d_in[21];
    const float* b_cfc2 = (const float*)d_in[22];
    float* out = (float*)d_out;

    float *p_qkv, *p_attn, *p_x, *p_x32, *p_ln32, *p_t, *p_cqkv, *p_co, *p_co2, *p_cmlp;
    __nv_bfloat16 *p_abf, *p_abf2, *p_wbf, *p_qs, *p_ks, *p_vt;
    cudaGetSymbolAddress((void**)&p_qkv,  g_qkv);
    cudaGetSymbolAddress((void**)&p_attn, g_attn);
    cudaGetSymbolAddress((void**)&p_x,    g_x);
    cudaGetSymbolAddress((void**)&p_x32,  g_x32);
    cudaGetSymbolAddress((void**)&p_ln32, g_ln32);
    cudaGetSymbolAddress((void**)&p_t,    g_t);
    cudaGetSymbolAddress((void**)&p_cqkv, g_cqkv);
    cudaGetSymbolAddress((void**)&p_co,   g_co);
    cudaGetSymbolAddress((void**)&p_co2,  g_co2);
    cudaGetSymbolAddress((void**)&p_cmlp, g_cmlp);
    cudaGetSymbolAddress((void**)&p_abf,  g_abf);
    cudaGetSymbolAddress((void**)&p_abf2, g_abf2);
    cudaGetSymbolAddress((void**)&p_wbf,  g_wbf);
    cudaGetSymbolAddress((void**)&p_qs,   g_qs);
    cudaGetSymbolAddress((void**)&p_ks,   g_ks);
    cudaGetSymbolAddress((void**)&p_vt,   g_vt);

    const int SM128 = 3 * (128 * 128 + 128 * 128) + 1024;
    const int SM32  = 3 * (128 * 128 + 32 * 128) + 1024;
    cudaFuncSetAttribute(gemm_mma<128, false, false, false>, cudaFuncAttributeMaxDynamicSharedMemorySize, SM128);
    cudaFuncSetAttribute(gemm_mma<128, false, true,  false>, cudaFuncAttributeMaxDynamicSharedMemorySize, SM128);
    cudaFuncSetAttribute(gemm_mma<128, true,  false, true >, cudaFuncAttributeMaxDynamicSharedMemorySize, SM128);
    cudaFuncSetAttribute(gemm_mma<32,  false, false, false>, cudaFuncAttributeMaxDynamicSharedMemorySize, SM32);
    cudaFuncSetAttribute(gemm_mma<32,  false, true,  false>, cudaFuncAttributeMaxDynamicSharedMemorySize, SM32);

    const int M = MROWS;
    const int MB = M / 128;

    // 1. LN1 -> [hi|lo]
    ln768_x2<<<M, 256>>>(x, g1, b1, p_abf);
    // 2. qkv
    conv_x2<<<cdiv((long long)3 * CC * CC / 4, 256), 256>>>(w_qkv, p_wbf, 3 * CC, CC);
    gemm_mma<128, false, false, false><<<dim3(18, MB), 256, SM128>>>(p_abf, p_wbf, nullptr, nullptr, p_qkv, nullptr, M, 3 * CC, CC);
    // 3. attention (HMMA bf16x3)
    conv_qk<<<cdiv((long long)NBH * 197 * 32, 256), 256>>>(p_qkv, p_qs, p_ks);
    conv_vt<<<NBH * 4, 256>>>(p_qkv, p_vt);
    attn_qk_mma<<<dim3(4, 4, NBH), 128>>>(p_qs, p_ks, p_attn);
    softmax197_warp<<<NBH * NN / 8, 256>>>(p_attn);
    attn_av_mma<<<dim3(4, NBH), 128>>>(p_attn, p_vt, p_abf);
    // 4. x = x_in + O @ w_proj^T + b_proj
    conv_x2<<<cdiv((long long)CC * CC / 4, 256), 256>>>(w_proj, p_wbf, CC, CC);
    gemm_mma<128, false, true, false><<<dim3(6, MB), 256, SM128>>>(p_abf, p_wbf, b_proj, x, p_x, nullptr, M, CC, CC);
    // 5. LN2 -> [hi|lo]
    ln768_x2<<<M, 256>>>(p_x, g2, b2, p_abf);
    // 6. hidden = gelu(...) -> [hi|lo] directly
    conv_x2<<<cdiv((long long)MLPH * CC / 4, 256), 256>>>(w_fc1, p_wbf, MLPH, CC);
    gemm_mma<128, true, false, true><<<dim3(24, MB), 256, SM128>>>(p_abf, p_wbf, b_fc1, nullptr, nullptr, p_abf2, M, MLPH, CC);
    // 7. x32 = hidden @ w_fc2^T + b_fc2
    conv_x2<<<cdiv((long long)OUTC * MLPH / 4, 256), 256>>>(w_fc2, p_wbf, OUTC, MLPH);
    gemm_mma<32, false, false, false><<<dim3(1, MB), 256, SM32>>>(p_abf2, p_wbf, b_fc2, nullptr, p_x32, nullptr, M, OUTC, MLPH);
    // 8. LN3
    ln32_kernel<<<M / 8, 256>>>(p_x32, g3, b3, p_ln32);
    // 9. channel branch
    make_t_kernel<<<(BB * OUTC * CNN + 255) / 256, 256>>>(p_ln32, p_t);
    gemm_nt<128, 128, 16, 8, 8, false, false><<<dim3(5, CMROWS / 128), 256>>>(p_t, w_cqkv, nullptr, nullptr, p_cqkv, CMROWS, 3 * CNN, CNN);
    chattn_kernel<<<BB * CHH, 256>>>(p_cqkv, p_co);
    gemm_nt<128, 128, 16, 8, 8, false, false><<<dim3(2, CMROWS / 128), 256>>>(p_co, w_cproj, b_cproj, nullptr, p_co2, CMROWS, CNN, CNN);
    concat_add_kernel<<<(M * OUTC + 255) / 256, 256>>>(p_ln32, p_co2, p_x32);
    // 10. LN4 + channel MLP
    ln32_kernel<<<M / 8, 256>>>(p_x32, g4, b4, p_ln32);
    gemm_nt<128, 128, 16, 8, 8, true, false><<<dim3(1, MB), 256>>>(p_ln32, w_cfc1, b_cfc1, nullptr, p_cmlp, M, CMLPH, OUTC);
    conv_x2<<<cdiv((long long)M * CMLPH / 4, 256), 256>>>(p_cmlp, p_abf, M, CMLPH);
    conv_x2<<<cdiv((long long)OUTC * CMLPH / 4, 256), 256>>>(w_cfc2, p_wbf, OUTC, CMLPH);
    gemm_mma<32, false, true, false><<<dim3(1, MB), 256, SM32>>>(p_abf, p_wbf, b_cfc2, p_x32, out, nullptr, M, OUTC, CMLPH);
}

// round 9
// speedup vs baseline: 1.0214x; 1.0214x over previous
#include <cuda_runtime.h>
#include <cuda_bf16.h>
#include <math.h>
#include <stdint.h>
#include <stddef.h>

#define BB   128
#define NN   197
#define CC   768
#define HH   12
#define HD   64
#define OUTC 32
#define CHH  14
#define CHD  14
#define CNN  196
#define MLPH 3072
#define CMLPH 128
#define MROWS (BB*NN)          // 25216
#define CMROWS (BB*OUTC)       // 4096
#define NBH   (BB*HH)          // 1536

// ---------------- scratch ----------------
__device__ float g_x   [MROWS*CC];
__device__ float g_x32 [MROWS*OUTC];
__device__ float g_ln32[MROWS*OUTC];
__device__ float g_t   [BB*OUTC*CNN];
__device__ float g_cqkv[BB*OUTC*3*CNN];
__device__ float g_co  [BB*OUTC*CNN];
__device__ float g_co2 [BB*OUTC*CNN];
__device__ float g_cmlp[MROWS*CMLPH];
__device__ __nv_bfloat16 g_abf [(size_t)MROWS*2*CC];    // [hi|lo] activations
__device__ __nv_bfloat16 g_abf2[(size_t)MROWS*2*MLPH];  // [hi|lo] mlp hidden
__device__ __nv_bfloat16 g_wbf [(size_t)MLPH*2*CC];     // [hi|lo] weights
__device__ __nv_bfloat16 g_qs  [(size_t)NBH*4*2*4096];  // Q slabs [hi|lo]
__device__ __nv_bfloat16 g_ks  [(size_t)NBH*4*2*4096];  // K slabs [hi|lo]
__device__ __nv_bfloat16 g_vt  [(size_t)NBH*4*2*4096];  // V^T slabs [hi|lo]
__device__ __nv_bfloat16 g_ps  [(size_t)NBH*4*4*2*4096];// P slabs [hi|lo]

__device__ __forceinline__ float gelu_f(float x) {
    return 0.5f * x * (1.0f + erff(x * 0.70710678118654752440f));
}

// ================= PTX helpers =================
__device__ __forceinline__ uint32_t smem_u32(const void* p) {
    uint32_t a;
    asm("{ .reg .u64 t; cvta.to.shared.u64 t, %1; cvt.u32.u64 %0, t; }" : "=r"(a) : "l"(p));
    return a;
}
#define CP_ASYNC16(d, s)    asm volatile("cp.async.cg.shared.global [%0], [%1], 16;" :: "r"(d), "l"(s))
#define CP_COMMIT()         asm volatile("cp.async.commit_group;" ::: "memory")
#define CP_WAIT1()          asm volatile("cp.async.wait_group 1;" ::: "memory")
#define CP_WAIT0()          asm volatile("cp.async.wait_group 0;" ::: "memory")

__device__ __forceinline__ void ldm_x4(uint32_t* r, uint32_t addr) {
    asm volatile("ldmatrix.sync.aligned.m8n8.x4.shared.b16 {%0,%1,%2,%3}, [%4];"
        : "=r"(r[0]), "=r"(r[1]), "=r"(r[2]), "=r"(r[3]) : "r"(addr));
}
__device__ __forceinline__ void mma_bf16(float* c, const uint32_t* a, const uint32_t* b) {
    asm volatile("mma.sync.aligned.m16n8k16.row.col.f32.bf16.bf16.f32 "
        "{%0,%1,%2,%3}, {%4,%5,%6,%7}, {%8,%9}, {%0,%1,%2,%3};"
        : "+f"(c[0]), "+f"(c[1]), "+f"(c[2]), "+f"(c[3])
        : "r"(a[0]), "r"(a[1]), "r"(a[2]), "r"(a[3]), "r"(b[0]), "r"(b[1]));
}
__device__ __forceinline__ uint32_t swz(uint32_t off) { return off ^ ((off >> 3) & 0x70); }
__device__ __forceinline__ void split2(float a, float b, __nv_bfloat162& hp, __nv_bfloat162& lp) {
    __nv_bfloat16 h0 = __float2bfloat16(a), h1 = __float2bfloat16(b);
    hp = __nv_bfloat162(h0, h1);
    lp = __nv_bfloat162(__float2bfloat16(a - __bfloat162float(h0)),
                        __float2bfloat16(b - __bfloat162float(h1)));
}

// ================= conversions =================
__global__ void conv_x2(const float* __restrict__ in, __nv_bfloat16* __restrict__ out,
                        int Mr, int K) {
    long long idx = (long long)blockIdx.x * 256 + threadIdx.x;
    long long tot = (long long)Mr * (K / 4);
    if (idx >= tot) return;
    int m = (int)(idx / (K / 4)), k = (int)(idx % (K / 4)) * 4;
    float4 v = *(const float4*)(in + (size_t)m * K + k);
    __nv_bfloat162 hp0, lp0, hp1, lp1;
    split2(v.x, v.y, hp0, lp0); split2(v.z, v.w, hp1, lp1);
    __nv_bfloat16* row = out + (size_t)m * 2 * K;
    *(__nv_bfloat162*)(row + k) = hp0;           *(__nv_bfloat162*)(row + k + 2) = hp1;
    *(__nv_bfloat162*)(row + K + k) = lp0;       *(__nv_bfloat162*)(row + K + k + 2) = lp1;
}

// ================= mma.sync bf16 NT GEMM, 2-slab storage, 3-pass chunks =================
// MODE: 0 = fp32 out (opt RES), 1 = [hi|lo] bf16 out, 2 = qkv slab scatter
template<int BN, bool GELU, bool RES, int MODE>
__global__ void __launch_bounds__(256, 2)
gemm_mma(const __nv_bfloat16* __restrict__ A, const __nv_bfloat16* __restrict__ Bw,
         const float* __restrict__ bias, const float* __restrict__ res,
         float* __restrict__ C, __nv_bfloat16* __restrict__ Cx2,
         __nv_bfloat16* __restrict__ qs, __nv_bfloat16* __restrict__ ks_,
         __nv_bfloat16* __restrict__ vt, int M, int N, int K) {
    constexpr int A_BYTES = 128 * 128;
    constexpr int B_BYTES = BN * 128;
    constexpr int STAGE = A_BYTES + B_BYTES;
    constexpr int NSTG = 3;
    constexpr int WN = BN / 2;
    constexpr int MF = 2;
    constexpr int NF = WN / 8;

    extern __shared__ char smraw[];
    char* sm = (char*)(((uintptr_t)smraw + 1023) & ~(uintptr_t)1023);
    uint32_t smb = smem_u32(sm);

    int tid = threadIdx.x, wid = tid >> 5, lane = tid & 31;
    int wm = wid & 3, wn = wid >> 2;
    int bm = blockIdx.y * 128, bn = blockIdx.x * BN;
    const __nv_bfloat16* Ab = A + (size_t)bm * 2 * K;
    const __nv_bfloat16* Bb = Bw + (size_t)bn * 2 * K;
    const int nch = K >> 5;

    auto load_chunk = [&](int c, int s) {
        int k0 = c << 5;
        uint32_t sa = smb + s * STAGE;
        #pragma unroll
        for (int i = 0; i < (128 * 8) / 256; i++) {
            int idx = tid + i * 256;
            int r = idx >> 3, u = idx & 7;
            const __nv_bfloat16* src = Ab + (size_t)r * 2 * K +
                ((u < 4) ? (k0 + u * 8) : (K + k0 + (u - 4) * 8));
            CP_ASYNC16(sa + swz((r << 7) | (u << 4)), (const char*)src);
        }
        uint32_t sb = sa + A_BYTES;
        #pragma unroll
        for (int i = 0; i < (BN * 8 + 255) / 256; i++) {
            int idx = tid + i * 256;
            if (BN * 8 % 256 == 0 || idx < BN * 8) {
                int r = idx >> 3, u = idx & 7;
                const __nv_bfloat16* src = Bb + (size_t)r * 2 * K +
                    ((u < 4) ? (k0 + u * 8) : (K + k0 + (u - 4) * 8));
                CP_ASYNC16(sb + swz((r << 7) | (u << 4)), (const char*)src);
            }
        }
    };

    float acc[MF][NF][4];
    #pragma unroll
    for (int i = 0; i < MF; i++)
        #pragma unroll
        for (int j = 0; j < NF; j++)
            #pragma unroll
            for (int e = 0; e < 4; e++) acc[i][j][e] = 0.0f;

    load_chunk(0, 0); CP_COMMIT();
    if (nch > 1) load_chunk(1, 1);
    CP_COMMIT();

    int a_mi = lane >> 3, a_r = lane & 7;
    int b_grp = lane >> 3, b_r = lane & 7;

    for (int c = 0; c < nch; c++) {
        CP_WAIT1();
        __syncthreads();
        if (c + 2 < nch) load_chunk(c + 2, (c + 2) % NSTG);
        CP_COMMIT();

        int s = c % NSTG;
        uint32_t sa = smb + s * STAGE;
        uint32_t sb = sa + A_BYTES;
        #pragma unroll
        for (int ksi = 0; ksi < 2; ksi++) {
            uint32_t afh[MF][4];
            #pragma unroll
            for (int mf = 0; mf < MF; mf++) {
                int row = wm * 32 + mf * 16 + ((a_mi & 1) << 3) + a_r;
                ldm_x4(afh[mf], sa + swz((row << 7) | ((ksi * 2 + (a_mi >> 1)) << 4)));
            }
            #pragma unroll
            for (int nfp = 0; nfp < NF / 2; nfp++) {
                uint32_t bfr[4];
                int row = wn * WN + (nfp * 2 + (b_grp >> 1)) * 8 + b_r;
                ldm_x4(bfr, sb + swz((row << 7) | ((ksi * 2 + (b_grp & 1)) << 4)));
                #pragma unroll
                for (int mf = 0; mf < MF; mf++) {
                    mma_bf16(acc[mf][nfp * 2 + 0], afh[mf], bfr);
                    mma_bf16(acc[mf][nfp * 2 + 1], afh[mf], bfr + 2);
                }
            }
            #pragma unroll
            for (int nfp = 0; nfp < NF / 2; nfp++) {
                uint32_t bfr[4];
                int row = wn * WN + (nfp * 2 + (b_grp >> 1)) * 8 + b_r;
                ldm_x4(bfr, sb + swz((row << 7) | ((4 + ksi * 2 + (b_grp & 1)) << 4)));
                #pragma unroll
                for (int mf = 0; mf < MF; mf++) {
                    mma_bf16(acc[mf][nfp * 2 + 0], afh[mf], bfr);
                    mma_bf16(acc[mf][nfp * 2 + 1], afh[mf], bfr + 2);
                }
            }
            uint32_t afl[MF][4];
            #pragma unroll
            for (int mf = 0; mf < MF; mf++) {
                int row = wm * 32 + mf * 16 + ((a_mi & 1) << 3) + a_r;
                ldm_x4(afl[mf], sa + swz((row << 7) | ((4 + ksi * 2 + (a_mi >> 1)) << 4)));
            }
            #pragma unroll
            for (int nfp = 0; nfp < NF / 2; nfp++) {
                uint32_t bfr[4];
                int row = wn * WN + (nfp * 2 + (b_grp >> 1)) * 8 + b_r;
                ldm_x4(bfr, sb + swz((row << 7) | ((ksi * 2 + (b_grp & 1)) << 4)));
                #pragma unroll
                for (int mf = 0; mf < MF; mf++) {
                    mma_bf16(acc[mf][nfp * 2 + 0], afl[mf], bfr);
                    mma_bf16(acc[mf][nfp * 2 + 1], afl[mf], bfr + 2);
                }
            }
        }
    }

    int cr = lane >> 2, cc2 = (lane & 3) << 1;
    #pragma unroll
    for (int mf = 0; mf < MF; mf++) {
        #pragma unroll
        for (int half = 0; half < 2; half++) {
            int gm = bm + wm * 32 + mf * 16 + cr + half * 8;
            #pragma unroll
            for (int nf = 0; nf < NF; nf++) {
                int gn = bn + wn * WN + nf * 8 + cc2;
                float v0 = acc[mf][nf][half * 2 + 0];
                float v1 = acc[mf][nf][half * 2 + 1];
                if (bias) { v0 += __ldg(&bias[gn]); v1 += __ldg(&bias[gn + 1]); }
                if (GELU) { v0 = gelu_f(v0); v1 = gelu_f(v1); }
                if (MODE == 1) {
                    __nv_bfloat162 hp, lp;
                    split2(v0, v1, hp, lp);
                    __nv_bfloat16* row = Cx2 + (size_t)gm * (2 * N);
                    *(__nv_bfloat162*)(row + gn) = hp;
                    *(__nv_bfloat162*)(row + N + gn) = lp;
                } else if (MODE == 2) {
                    int b = gm / NN, n = gm - b * NN;
                    int part = gn / CC, w = gn - part * CC;
                    int h = w >> 6, d = w & 63;
                    int tile = n >> 6, r = n & 63;
                    int bh = b * HH + h;
                    __nv_bfloat162 hp, lp;
                    split2(v0, v1, hp, lp);
                    size_t sbase = ((size_t)(bh * 4 + tile)) * 2 * 4096;
                    if (part == 0) {
                        *(__nv_bfloat162*)(qs + sbase + r * 64 + d) = hp;
                        *(__nv_bfloat162*)(qs + sbase + 4096 + r * 64 + d) = lp;
                    } else if (part == 1) {
                        *(__nv_bfloat162*)(ks_ + sbase + r * 64 + d) = hp;
                        *(__nv_bfloat162*)(ks_ + sbase + 4096 + r * 64 + d) = lp;
                    } else {
                        vt[sbase + d * 64 + r] = hp.x;
                        vt[sbase + (d + 1) * 64 + r] = hp.y;
                        vt[sbase + 4096 + d * 64 + r] = lp.x;
                        vt[sbase + 4096 + (d + 1) * 64 + r] = lp.y;
                    }
                } else {
                    if (RES) {
                        float2 rv = *(const float2*)(res + (size_t)gm * N + gn);
                        v0 += rv.x; v1 += rv.y;
                    }
                    *(float2*)(C + (size_t)gm * N + gn) = make_float2(v0, v1);
                }
            }
        }
    }
}

// ================= fused QK + softmax + P-split =================
// one CTA per (qt, bh): full 64x256 score block, register softmax, write P [hi|lo] slabs
__global__ void __launch_bounds__(128)
attn_qks(const __nv_bfloat16* __restrict__ Qs, const __nv_bfloat16* __restrict__ Ks,
         __nv_bfloat16* __restrict__ Ps) {
    __shared__ __align__(128) char sm[32768];
    uint32_t smb = smem_u32(sm);
    uint32_t smQ = smb, smK = smb + 16384;
    int qt = blockIdx.x, bh = blockIdx.y;
    int tid = threadIdx.x, wid = tid >> 5, lane = tid & 31;
    int a_mi = lane >> 3, a_r = lane & 7, b_grp = lane >> 3, b_r = lane & 7;

    const char* Qb = (const char*)(Qs + ((size_t)(bh * 4 + qt)) * 2 * 4096);
    for (int c = tid; c < 1024; c += 128) {
        int slab = c >> 9, rem = c & 511, row = rem >> 3, unit = rem & 7;
        CP_ASYNC16(smQ + slab * 8192 + swz((row << 7) | (unit << 4)), Qb + (size_t)c * 16);
    }
    CP_COMMIT();

    float acc[4][8][4];
    #pragma unroll
    for (int kt = 0; kt < 4; kt++)
        #pragma unroll
        for (int nf = 0; nf < 8; nf++)
            #pragma unroll
            for (int e = 0; e < 4; e++) acc[kt][nf][e] = 0.f;

    const int pa[3] = {0, 0, 1}, pb[3] = {0, 1, 0};
    for (int kt = 0; kt < 4; kt++) {
        const char* Kb = (const char*)(Ks + ((size_t)(bh * 4 + kt)) * 2 * 4096);
        for (int c = tid; c < 1024; c += 128) {
            int slab = c >> 9, rem = c & 511, row = rem >> 3, unit = rem & 7;
            CP_ASYNC16(smK + slab * 8192 + swz((row << 7) | (unit << 4)), Kb + (size_t)c * 16);
        }
        CP_COMMIT(); CP_WAIT0();
        __syncthreads();
        #pragma unroll
        for (int p = 0; p < 3; p++) {
            #pragma unroll
            for (int ksi = 0; ksi < 4; ksi++) {
                uint32_t afr[4];
                int arow = wid * 16 + ((a_mi & 1) << 3) + a_r;
                ldm_x4(afr, smQ + pa[p] * 8192 + swz((arow << 7) | ((ksi * 2 + (a_mi >> 1)) << 4)));
                #pragma unroll
                for (int nfp = 0; nfp < 4; nfp++) {
                    uint32_t bfr[4];
                    int brow = (nfp * 2 + (b_grp >> 1)) * 8 + b_r;
                    ldm_x4(bfr, smK + pb[p] * 8192 + swz((brow << 7) | ((ksi * 2 + (b_grp & 1)) << 4)));
                    mma_bf16(acc[kt][nfp * 2 + 0], afr, bfr);
                    mma_bf16(acc[kt][nfp * 2 + 1], afr, bfr + 2);
                }
            }
        }
        __syncthreads();
    }

    int cr = lane >> 2, cc2 = (lane & 3) << 1;
    // scale + mask
    #pragma unroll
    for (int kt = 0; kt < 4; kt++)
        #pragma unroll
        for (int nf = 0; nf < 8; nf++)
            #pragma unroll
            for (int e = 0; e < 4; e++) {
                int k = kt * 64 + nf * 8 + cc2 + (e & 1);
                float s = acc[kt][nf][e] * 0.125f;
                acc[kt][nf][e] = (k < NN) ? s : -INFINITY;
            }
    // register softmax over two rows per thread
    float mx0 = -INFINITY, mx1 = -INFINITY;
    #pragma unroll
    for (int kt = 0; kt < 4; kt++)
        #pragma unroll
        for (int nf = 0; nf < 8; nf++) {
            mx0 = fmaxf(mx0, fmaxf(acc[kt][nf][0], acc[kt][nf][1]));
            mx1 = fmaxf(mx1, fmaxf(acc[kt][nf][2], acc[kt][nf][3]));
        }
    #pragma unroll
    for (int o = 1; o <= 2; o <<= 1) {
        mx0 = fmaxf(mx0, __shfl_xor_sync(0xffffffff, mx0, o));
        mx1 = fmaxf(mx1, __shfl_xor_sync(0xffffffff, mx1, o));
    }
    float s0 = 0.f, s1 = 0.f;
    #pragma unroll
    for (int kt = 0; kt < 4; kt++)
        #pragma unroll
        for (int nf = 0; nf < 8; nf++) {
            float e0 = __expf(acc[kt][nf][0] - mx0);
            float e1 = __expf(acc[kt][nf][1] - mx0);
            float e2 = __expf(acc[kt][nf][2] - mx1);
            float e3 = __expf(acc[kt][nf][3] - mx1);
            acc[kt][nf][0] = e0; acc[kt][nf][1] = e1;
            acc[kt][nf][2] = e2; acc[kt][nf][3] = e3;
            s0 += e0 + e1; s1 += e2 + e3;
        }
    #pragma unroll
    for (int o = 1; o <= 2; o <<= 1) {
        s0 += __shfl_xor_sync(0xffffffff, s0, o);
        s1 += __shfl_xor_sync(0xffffffff, s1, o);
    }
    float inv0 = 1.0f / s0, inv1 = 1.0f / s1;

    __nv_bfloat16* base = Ps + ((size_t)(bh * 4 + qt) * 4) * 2 * 4096;
    int r0 = wid * 16 + cr, r1 = r0 + 8;
    #pragma unroll
    for (int kt = 0; kt < 4; kt++) {
        #pragma unroll
        for (int nf = 0; nf < 8; nf++) {
            int col = nf * 8 + cc2;
            __nv_bfloat162 hp, lp;
            split2(acc[kt][nf][0] * inv0, acc[kt][nf][1] * inv0, hp, lp);
            size_t off = (size_t)kt * 2 * 4096 + r0 * 64 + col;
            *(__nv_bfloat162*)(base + off) = hp;
            *(__nv_bfloat162*)(base + off + 4096) = lp;
            split2(acc[kt][nf][2] * inv1, acc[kt][nf][3] * inv1, hp, lp);
            off = (size_t)kt * 2 * 4096 + r1 * 64 + col;
            *(__nv_bfloat162*)(base + off) = hp;
            *(__nv_bfloat162*)(base + off + 4096) = lp;
        }
    }
}

// ================= AV: pure cp.async, 3-pass 2-slab =================
__global__ void __launch_bounds__(128)
attn_av(const __nv_bfloat16* __restrict__ Ps, const __nv_bfloat16* __restrict__ Vt,
        __nv_bfloat16* __restrict__ Ox2) {
    __shared__ __align__(128) char sm[32768];
    uint32_t smb = smem_u32(sm);
    uint32_t smP = smb, smV = smb + 16384;
    int qt = blockIdx.x, bh = blockIdx.y;
    int b = bh / HH, h = bh % HH;
    int tid = threadIdx.x, wid = tid >> 5, lane = tid & 31;
    int a_mi = lane >> 3, a_r = lane & 7, b_grp = lane >> 3, b_r = lane & 7;
    float acc[8][4];
    #pragma unroll
    for (int i = 0; i < 8; i++)
        #pragma unroll
        for (int e = 0; e < 4; e++) acc[i][e] = 0.f;

    const int pa[3] = {0, 0, 1}, pb[3] = {0, 1, 0};
    for (int kt = 0; kt < 4; kt++) {
        const char* Pb = (const char*)(Ps + ((size_t)((bh * 4 + qt) * 4 + kt)) * 2 * 4096);
        const char* Vb = (const char*)(Vt + ((size_t)(bh * 4 + kt)) * 2 * 4096);
        for (int c = tid; c < 1024; c += 128) {
            int slab = c >> 9, rem = c & 511, row = rem >> 3, unit = rem & 7;
            uint32_t off = slab * 8192 + swz((row << 7) | (unit << 4));
            CP_ASYNC16(smP + off, Pb + (size_t)c * 16);
            CP_ASYNC16(smV + off, Vb + (size_t)c * 16);
        }
        CP_COMMIT(); CP_WAIT0();
        __syncthreads();
        #pragma unroll
        for (int p = 0; p < 3; p++) {
            #pragma unroll
            for (int ksi = 0; ksi < 4; ksi++) {
                uint32_t afr[4];
                int arow = wid * 16 + ((a_mi & 1) << 3) + a_r;
                ldm_x4(afr, smP + pa[p] * 8192 + swz((arow << 7) | ((ksi * 2 + (a_mi >> 1)) << 4)));
                #pragma unroll
                for (int nfp = 0; nfp < 4; nfp++) {
                    uint32_t bfr[4];
                    int brow = (nfp * 2 + (b_grp >> 1)) * 8 + b_r;
                    ldm_x4(bfr, smV + pb[p] * 8192 + swz((brow << 7) | ((ksi * 2 + (b_grp & 1)) << 4)));
                    mma_bf16(acc[nfp * 2 + 0], afr, bfr);
                    mma_bf16(acc[nfp * 2 + 1], afr, bfr + 2);
                }
            }
        }
        __syncthreads();
    }
    int cr = lane >> 2, cc2 = (lane & 3) << 1;
    #pragma unroll
    for (int nf = 0; nf < 8; nf++) {
        #pragma unroll
        for (int half = 0; half < 2; half++) {
            int q = qt * 64 + wid * 16 + cr + half * 8;
            if (q < NN) {
                int m = b * NN + q;
                int col = h * HD + nf * 8 + cc2;
                __nv_bfloat162 hp, lp;
                split2(acc[nf][half * 2 + 0], acc[nf][half * 2 + 1], hp, lp);
                __nv_bfloat16* row = Ox2 + (size_t)m * (2 * CC);
                *(__nv_bfloat162*)(row + col) = hp;
                *(__nv_bfloat162*)(row + CC + col) = lp;
            }
        }
    }
}

// ---------------- LayerNorm D=768 -> [hi|lo] ----------------
__global__ void ln768_x2(const float* __restrict__ x, const float* __restrict__ g,
                         const float* __restrict__ b, __nv_bfloat16* __restrict__ out) {
    int row = blockIdx.x;
    const float* p = x + (size_t)row * CC;
    int tid = threadIdx.x;
    float v0 = p[tid], v1 = p[tid + 256], v2 = p[tid + 512];
    float s = v0 + v1 + v2;
    float sq = v0 * v0 + v1 * v1 + v2 * v2;
    __shared__ float rs[256], rq[256];
    rs[tid] = s; rq[tid] = sq; __syncthreads();
    for (int st = 128; st > 0; st >>= 1) {
        if (tid < st) { rs[tid] += rs[tid + st]; rq[tid] += rq[tid + st]; }
        __syncthreads();
    }
    float mean = rs[0] * (1.0f / CC);
    float var  = rq[0] * (1.0f / CC) - mean * mean;
    float inv = rsqrtf(var + 1e-5f);
    __nv_bfloat16* o = out + (size_t)row * (2 * CC);
    #pragma unroll
    for (int j = 0; j < 3; j++) {
        int c = tid + j * 256;
        float y = (p[c] - mean) * inv * g[c] + b[c];
        __nv_bfloat16 hi = __float2bfloat16(y);
        o[c] = hi;
        o[CC + c] = __float2bfloat16(y - __bfloat162float(hi));
    }
}

// ---------------- LayerNorm D=32 ----------------
__global__ void ln32_kernel(const float* __restrict__ x, const float* __restrict__ g,
                            const float* __restrict__ b, float* __restrict__ out) {
    int row = blockIdx.x * 8 + threadIdx.x / 32;
    int lane = threadIdx.x & 31;
    float v = x[(size_t)row * OUTC + lane];
    float s = v, sq = v * v;
    #pragma unroll
    for (int o = 16; o > 0; o >>= 1) {
        s  += __shfl_xor_sync(0xffffffff, s, o);
        sq += __shfl_xor_sync(0xffffffff, sq, o);
    }
    float mean = s * (1.0f / OUTC);
    float var  = sq * (1.0f / OUTC) - mean * mean;
    float inv = rsqrtf(var + 1e-5f);
    out[(size_t)row * OUTC + lane] = (v - mean) * inv * g[lane] + b[lane];
}

// ---------------- fp32 SIMT GEMM (small channel GEMMs) ----------------
template<int BM, int BN, int BK, int TM, int TN, bool GELU, bool RES>
__global__ void gemm_nt(const float* __restrict__ A, const float* __restrict__ Bw,
                        const float* __restrict__ bias, const float* __restrict__ res,
                        float* __restrict__ C, int M, int N, int K) {
    constexpr int THREADS = (BM / TM) * (BN / TN);
    __shared__ float As[BK][BM];
    __shared__ float Bs[BK][BN];
    int tid = threadIdx.x;
    int bm = blockIdx.y * BM, bn = blockIdx.x * BN;
    int tx = tid % (BN / TN), ty = tid / (BN / TN);
    float acc[TM][TN];
    #pragma unroll
    for (int i = 0; i < TM; i++)
        #pragma unroll
        for (int j = 0; j < TN; j++) acc[i][j] = 0.0f;
    constexpr int A4 = BM * BK / 4;
    constexpr int B4 = BN * BK / 4;
    for (int k0 = 0; k0 < K; k0 += BK) {
        #pragma unroll
        for (int i = tid; i < A4; i += THREADS) {
            int row = i / (BK / 4);
            int kk  = (i % (BK / 4)) * 4;
            float4 v = make_float4(0.f, 0.f, 0.f, 0.f);
            if (k0 + kk < K) v = *(const float4*)(A + (size_t)(bm + row) * K + k0 + kk);
            As[kk + 0][row] = v.x; As[kk + 1][row] = v.y;
            As[kk + 2][row] = v.z; As[kk + 3][row] = v.w;
        }
        #pragma unroll
        for (int i = tid; i < B4; i += THREADS) {
            int row = i / (BK / 4);
            int kk  = (i % (BK / 4)) * 4;
            float4 v = make_float4(0.f, 0.f, 0.f, 0.f);
            if (bn + row < N && k0 + kk < K)
                v = *(const float4*)(Bw + (size_t)(bn + row) * K + k0 + kk);
            Bs[kk + 0][row] = v.x; Bs[kk + 1][row] = v.y;
            Bs[kk + 2][row] = v.z; Bs[kk + 3][row] = v.w;
        }
        __syncthreads();
        #pragma unroll
        for (int kk = 0; kk < BK; kk++) {
            float a[TM], bv[TN];
            #pragma unroll
            for (int i = 0; i < TM; i++) a[i] = As[kk][ty * TM + i];
            #pragma unroll
            for (int j = 0; j < TN; j++) bv[j] = Bs[kk][tx * TN + j];
            #pragma unroll
            for (int i = 0; i < TM; i++)
                #pragma unroll
                for (int j = 0; j < TN; j++) acc[i][j] += a[i] * bv[j];
        }
        __syncthreads();
    }
    #pragma unroll
    for (int i = 0; i < TM; i++) {
        int gm = bm + ty * TM + i;
        #pragma unroll
        for (int j = 0; j < TN; j++) {
            int gn = bn + tx * TN + j;
            if (gn < N) {
                float v = acc[i][j];
                if (bias) v += bias[gn];
                if (GELU) v = gelu_f(v);
                if (RES) v += res[(size_t)gm * N + gn];
                C[(size_t)gm * N + gn] = v;
            }
        }
    }
}

// ---------------- t[b,c,s] = ln3[b, 1+s, c] ----------------
__global__ void make_t_kernel(const float* __restrict__ ln3, float* __restrict__ t) {
    int idx = blockIdx.x * 256 + threadIdx.x;
    if (idx >= BB * OUTC * CNN) return;
    int s = idx % CNN;
    int c = (idx / CNN) % OUTC;
    int b = idx / (CNN * OUTC);
    t[idx] = ln3[((size_t)(b * NN + 1 + s)) * OUTC + c];
}

// ---------------- tiny channel attention ----------------
__global__ void chattn_kernel(const float* __restrict__ cqkv, float* __restrict__ co) {
    int b = blockIdx.x / CHH, h = blockIdx.x % CHH;
    int tid = threadIdx.x;
    __shared__ float Q[OUTC][CHD], Kk[OUTC][CHD], V[OUTC][CHD], S[OUTC][OUTC + 1];
    const float* base = cqkv + (size_t)b * OUTC * (3 * CNN);
    for (int i = tid; i < OUTC * CHD; i += 256) {
        int r = i / CHD, d = i % CHD;
        Q[r][d]  = base[r * (3 * CNN) + h * CHD + d];
        Kk[r][d] = base[r * (3 * CNN) + CNN + h * CHD + d];
        V[r][d]  = base[r * (3 * CNN) + 2 * CNN + h * CHD + d];
    }
    __syncthreads();
    const float sc = rsqrtf((float)CHD);
    for (int i = tid; i < OUTC * OUTC; i += 256) {
        int qi = i / OUTC, kj = i % OUTC;
        float s = 0.0f;
        #pragma unroll
        for (int d = 0; d < CHD; d++) s += Q[qi][d] * Kk[kj][d];
        S[qi][kj] = s * sc;
    }
    __syncthreads();
    if (tid < OUTC) {
        float mx = -INFINITY;
        #pragma unroll
        for (int j = 0; j < OUTC; j++) mx = fmaxf(mx, S[tid][j]);
        float sum = 0.0f;
        #pragma unroll
        for (int j = 0; j < OUTC; j++) { float e = __expf(S[tid][j] - mx); S[tid][j] = e; sum += e; }
        float inv = 1.0f / sum;
        #pragma unroll
        for (int j = 0; j < OUTC; j++) S[tid][j] *= inv;
    }
    __syncthreads();
    for (int i = tid; i < OUTC * CHD; i += 256) {
        int qi = i / CHD, d = i % CHD;
        float s = 0.0f;
        #pragma unroll
        for (int kk = 0; kk < OUTC; kk++) s += S[qi][kk] * V[kk][d];
        co[((size_t)(b * OUTC + qi)) * CNN + h * CHD + d] = s;
    }
}

// ---------------- x32 += concat([ln3 cls, co2^T]) ----------------
__global__ void concat_add_kernel(const float* __restrict__ ln3, const float* __restrict__ co2,
                                  float* __restrict__ x32) {
    int idx = blockIdx.x * 256 + threadIdx.x;
    if (idx >= MROWS * OUTC) return;
    int c = idx % OUTC;
    int n = (idx / OUTC) % NN;
    int b = idx / (OUTC * NN);
    float add;
    if (n == 0) add = ln3[((size_t)b * NN) * OUTC + c];
    else        add = co2[((size_t)(b * OUTC + c)) * CNN + (n - 1)];
    x32[idx] += add;
}

// ---------------- launch ----------------
static inline int cdiv(long long a, int b) { return (int)((a + b - 1) / b); }

extern "C" void kernel_launch(void* const* d_in, const int* in_sizes, int n_in,
                              void* d_out, int out_size) {
    const float* x      = (const float*)d_in[0];
    const float* g1     = (const float*)d_in[1];
    const float* b1     = (const float*)d_in[2];
    const float* w_qkv  = (const float*)d_in[3];
    const float* w_proj = (const float*)d_in[4];
    const float* b_proj = (const float*)d_in[5];
    const float* g2     = (const float*)d_in[6];
    const float* b2     = (const float*)d_in[7];
    const float* w_fc1  = (const float*)d_in[8];
    const float* b_fc1  = (const float*)d_in[9];
    const float* w_fc2  = (const float*)d_in[10];
    const float* b_fc2  = (const float*)d_in[11];
    const float* g3     = (const float*)d_in[12];
    const float* b3     = (const float*)d_in[13];
    const float* w_cqkv = (const float*)d_in[14];
    const float* w_cproj= (const float*)d_in[15];
    const float* b_cproj= (const float*)d_in[16];
    const float* g4     = (const float*)d_in[17];
    const float* b4     = (const float*)d_in[18];
    const float* w_cfc1 = (const float*)d_in[19];
    const float* b_cfc1 = (const float*)d_in[20];
    const float* w_cfc2 = (const float*)d_in[21];
    const float* b_cfc2 = (const float*)d_in[22];
    float* out = (float*)d_out;

    float *p_x, *p_x32, *p_ln32, *p_t, *p_cqkv, *p_co, *p_co2, *p_cmlp;
    __nv_bfloat16 *p_abf, *p_abf2, *p_wbf, *p_qs, *p_ks, *p_vt, *p_ps;
    cudaGetSymbolAddress((void**)&p_x,    g_x);
    cudaGetSymbolAddress((void**)&p_x32,  g_x32);
    cudaGetSymbolAddress((void**)&p_ln32, g_ln32);
    cudaGetSymbolAddress((void**)&p_t,    g_t);
    cudaGetSymbolAddress((void**)&p_cqkv, g_cqkv);
    cudaGetSymbolAddress((void**)&p_co,   g_co);
    cudaGetSymbolAddress((void**)&p_co2,  g_co2);
    cudaGetSymbolAddress((void**)&p_cmlp, g_cmlp);
    cudaGetSymbolAddress((void**)&p_abf,  g_abf);
    cudaGetSymbolAddress((void**)&p_abf2, g_abf2);
    cudaGetSymbolAddress((void**)&p_wbf,  g_wbf);
    cudaGetSymbolAddress((void**)&p_qs,   g_qs);
    cudaGetSymbolAddress((void**)&p_ks,   g_ks);
    cudaGetSymbolAddress((void**)&p_vt,   g_vt);
    cudaGetSymbolAddress((void**)&p_ps,   g_ps);

    const int SM128 = 3 * (128 * 128 + 128 * 128) + 1024;
    const int SM32  = 3 * (128 * 128 + 32 * 128) + 1024;
    cudaFuncSetAttribute(gemm_mma<128, false, false, 2>, cudaFuncAttributeMaxDynamicSharedMemorySize, SM128);
    cudaFuncSetAttribute(gemm_mma<128, false, true,  0>, cudaFuncAttributeMaxDynamicSharedMemorySize, SM128);
    cudaFuncSetAttribute(gemm_mma<128, true,  false, 1>, cudaFuncAttributeMaxDynamicSharedMemorySize, SM128);
    cudaFuncSetAttribute(gemm_mma<32,  false, false, 0>, cudaFuncAttributeMaxDynamicSharedMemorySize, SM32);
    cudaFuncSetAttribute(gemm_mma<32,  false, true,  0>, cudaFuncAttributeMaxDynamicSharedMemorySize, SM32);

    const int M = MROWS;
    const int MB = M / 128;

    // 1. LN1 -> [hi|lo]
    ln768_x2<<<M, 256>>>(x, g1, b1, p_abf);
    // 2. qkv GEMM, epilogue writes Q/K/V slabs directly
    conv_x2<<<cdiv((long long)3 * CC * CC / 4, 256), 256>>>(w_qkv, p_wbf, 3 * CC, CC);
    gemm_mma<128, false, false, 2><<<dim3(18, MB), 256, SM128>>>(
        p_abf, p_wbf, nullptr, nullptr, nullptr, nullptr, p_qs, p_ks, p_vt, M, 3 * CC, CC);
    // 3. fused QK+softmax+split, then AV
    attn_qks<<<dim3(4, NBH), 128>>>(p_qs, p_ks, p_ps);
    attn_av<<<dim3(4, NBH), 128>>>(p_ps, p_vt, p_abf);
    // 4. x = x_in + O @ w_proj^T + b_proj
    conv_x2<<<cdiv((long long)CC * CC / 4, 256), 256>>>(w_proj, p_wbf, CC, CC);
    gemm_mma<128, false, true, 0><<<dim3(6, MB), 256, SM128>>>(
        p_abf, p_wbf, b_proj, x, p_x, nullptr, nullptr, nullptr, nullptr, M, CC, CC);
    // 5. LN2 -> [hi|lo]
    ln768_x2<<<M, 256>>>(p_x, g2, b2, p_abf);
    // 6. hidden = gelu(...) -> [hi|lo]
    conv_x2<<<cdiv((long long)MLPH * CC / 4, 256), 256>>>(w_fc1, p_wbf, MLPH, CC);
    gemm_mma<128, true, false, 1><<<dim3(24, MB), 256, SM128>>>(
        p_abf, p_wbf, b_fc1, nullptr, nullptr, p_abf2, nullptr, nullptr, nullptr, M, MLPH, CC);
    // 7. x32 = hidden @ w_fc2^T + b_fc2
    conv_x2<<<cdiv((long long)OUTC * MLPH / 4, 256), 256>>>(w_fc2, p_wbf, OUTC, MLPH);
    gemm_mma<32, false, false, 0><<<dim3(1, MB), 256, SM32>>>(
        p_abf2, p_wbf, b_fc2, nullptr, p_x32, nullptr, nullptr, nullptr, nullptr, M, OUTC, MLPH);
    // 8. LN3
    ln32_kernel<<<M / 8, 256>>>(p_x32, g3, b3, p_ln32);
    // 9. channel branch
    make_t_kernel<<<(BB * OUTC * CNN + 255) / 256, 256>>>(p_ln32, p_t);
    gemm_nt<128, 128, 16, 8, 8, false, false><<<dim3(5, CMROWS / 128), 256>>>(p_t, w_cqkv, nullptr, nullptr, p_cqkv, CMROWS, 3 * CNN, CNN);
    chattn_kernel<<<BB * CHH, 256>>>(p_cqkv, p_co);
    gemm_nt<128, 128, 16, 8, 8, false, false><<<dim3(2, CMROWS / 128), 256>>>(p_co, w_cproj, b_cproj, nullptr, p_co2, CMROWS, CNN, CNN);
    concat_add_kernel<<<(M * OUTC + 255) / 256, 256>>>(p_ln32, p_co2, p_x32);
    // 10. LN4 + channel MLP
    ln32_kernel<<<M / 8, 256>>>(p_x32, g4, b4, p_ln32);
    gemm_nt<128, 128, 16, 8, 8, true, false><<<dim3(1, MB), 256>>>(p_ln32, w_cfc1, b_cfc1, nullptr, p_cmlp, M, CMLPH, OUTC);
    conv_x2<<<cdiv((long long)M * CMLPH / 4, 256), 256>>>(p_cmlp, p_abf, M, CMLPH);
    conv_x2<<<cdiv((long long)OUTC * CMLPH / 4, 256), 256>>>(w_cfc2, p_wbf, OUTC, CMLPH);
    gemm_mma<32, false, true, 0><<<dim3(1, MB), 256, SM32>>>(
        p_abf, p_wbf, b_cfc2, p_x32, out, nullptr, nullptr, nullptr, nullptr, M, OUTC, CMLPH);
}

// round 10
// speedup vs baseline: 1.0305x; 1.0089x over previous
#include <cuda_runtime.h>
#include <cuda_bf16.h>
#include <math.h>
#include <stdint.h>
#include <stddef.h>

#define BB   128
#define NN   197
#define CC   768
#define HH   12
#define HD   64
#define OUTC 32
#define CHH  14
#define CHD  14
#define CNN  196
#define MLPH 3072
#define CMLPH 128
#define MROWS (BB*NN)          // 25216
#define CMROWS (BB*OUTC)       // 4096
#define NBH   (BB*HH)          // 1536

// ---------------- scratch ----------------
__device__ float g_x   [MROWS*CC];
__device__ float g_x32 [MROWS*OUTC];
__device__ float g_ln32[MROWS*OUTC];
__device__ float g_t   [BB*OUTC*CNN];
__device__ float g_cqkv[BB*OUTC*3*CNN];
__device__ float g_co  [BB*OUTC*CNN];
__device__ float g_co2 [BB*OUTC*CNN];
__device__ float g_cmlp[MROWS*CMLPH];
__device__ __nv_bfloat16 g_abf [(size_t)MROWS*2*CC];
__device__ __nv_bfloat16 g_abf2[(size_t)MROWS*2*MLPH];
__device__ __nv_bfloat16 g_wbf [(size_t)MLPH*2*CC];
__device__ __nv_bfloat16 g_qs  [(size_t)NBH*4*2*4096];
__device__ __nv_bfloat16 g_ks  [(size_t)NBH*4*2*4096];
__device__ __nv_bfloat16 g_vt  [(size_t)NBH*4*2*4096];
__device__ __nv_bfloat16 g_ps  [(size_t)NBH*4*4*2*4096];

__device__ __forceinline__ float gelu_f(float x) {
    return 0.5f * x * (1.0f + erff(x * 0.70710678118654752440f));
}

// ================= PTX helpers =================
__device__ __forceinline__ uint32_t smem_u32(const void* p) {
    uint32_t a;
    asm("{ .reg .u64 t; cvta.to.shared.u64 t, %1; cvt.u32.u64 %0, t; }" : "=r"(a) : "l"(p));
    return a;
}
#define CP_ASYNC16(d, s)    asm volatile("cp.async.cg.shared.global [%0], [%1], 16;" :: "r"(d), "l"(s))
#define CP_COMMIT()         asm volatile("cp.async.commit_group;" ::: "memory")
#define CP_WAIT1()          asm volatile("cp.async.wait_group 1;" ::: "memory")
#define CP_WAIT0()          asm volatile("cp.async.wait_group 0;" ::: "memory")

__device__ __forceinline__ void ldm_x4(uint32_t* r, uint32_t addr) {
    asm volatile("ldmatrix.sync.aligned.m8n8.x4.shared.b16 {%0,%1,%2,%3}, [%4];"
        : "=r"(r[0]), "=r"(r[1]), "=r"(r[2]), "=r"(r[3]) : "r"(addr));
}
__device__ __forceinline__ void mma_bf16(float* c, const uint32_t* a, const uint32_t* b) {
    asm volatile("mma.sync.aligned.m16n8k16.row.col.f32.bf16.bf16.f32 "
        "{%0,%1,%2,%3}, {%4,%5,%6,%7}, {%8,%9}, {%0,%1,%2,%3};"
        : "+f"(c[0]), "+f"(c[1]), "+f"(c[2]), "+f"(c[3])
        : "r"(a[0]), "r"(a[1]), "r"(a[2]), "r"(a[3]), "r"(b[0]), "r"(b[1]));
}
__device__ __forceinline__ uint32_t swz(uint32_t off) { return off ^ ((off >> 3) & 0x70); }
__device__ __forceinline__ void split2(float a, float b, __nv_bfloat162& hp, __nv_bfloat162& lp) {
    __nv_bfloat16 h0 = __float2bfloat16(a), h1 = __float2bfloat16(b);
    hp = __nv_bfloat162(h0, h1);
    lp = __nv_bfloat162(__float2bfloat16(a - __bfloat162float(h0)),
                        __float2bfloat16(b - __bfloat162float(h1)));
}

// ================= conversions =================
__global__ void conv_x2(const float* __restrict__ in, __nv_bfloat16* __restrict__ out,
                        int Mr, int K) {
    long long idx = (long long)blockIdx.x * 256 + threadIdx.x;
    long long tot = (long long)Mr * (K / 4);
    if (idx >= tot) return;
    int m = (int)(idx / (K / 4)), k = (int)(idx % (K / 4)) * 4;
    float4 v = *(const float4*)(in + (size_t)m * K + k);
    __nv_bfloat162 hp0, lp0, hp1, lp1;
    split2(v.x, v.y, hp0, lp0); split2(v.z, v.w, hp1, lp1);
    __nv_bfloat16* row = out + (size_t)m * 2 * K;
    *(__nv_bfloat162*)(row + k) = hp0;           *(__nv_bfloat162*)(row + k + 2) = hp1;
    *(__nv_bfloat162*)(row + K + k) = lp0;       *(__nv_bfloat162*)(row + K + k + 2) = lp1;
}

// ================= mma.sync bf16 NT GEMM, 2-slab storage, 3-pass chunks =================
// MODE: 0 = fp32 out (opt RES), 1 = [hi|lo] bf16 out, 2 = qkv slab scatter
template<int BN, bool GELU, bool RES, int MODE>
__global__ void __launch_bounds__(256, 2)
gemm_mma(const __nv_bfloat16* __restrict__ A, const __nv_bfloat16* __restrict__ Bw,
         const float* __restrict__ bias, const float* __restrict__ res,
         float* __restrict__ C, __nv_bfloat16* __restrict__ Cx2,
         __nv_bfloat16* __restrict__ qs, __nv_bfloat16* __restrict__ ks_,
         __nv_bfloat16* __restrict__ vt, int M, int N, int K) {
    constexpr int A_BYTES = 128 * 128;
    constexpr int B_BYTES = BN * 128;
    constexpr int STAGE = A_BYTES + B_BYTES;
    constexpr int NSTG = 3;
    constexpr int WN = BN / 2;
    constexpr int MF = 2;
    constexpr int NF = WN / 8;

    extern __shared__ char smraw[];
    char* sm = (char*)(((uintptr_t)smraw + 1023) & ~(uintptr_t)1023);
    uint32_t smb = smem_u32(sm);

    int tid = threadIdx.x, wid = tid >> 5, lane = tid & 31;
    int wm = wid & 3, wn = wid >> 2;
    int bm = blockIdx.y * 128, bn = blockIdx.x * BN;
    const __nv_bfloat16* Ab = A + (size_t)bm * 2 * K;
    const __nv_bfloat16* Bb = Bw + (size_t)bn * 2 * K;
    const int nch = K >> 5;

    auto load_chunk = [&](int c, int s) {
        int k0 = c << 5;
        uint32_t sa = smb + s * STAGE;
        #pragma unroll
        for (int i = 0; i < (128 * 8) / 256; i++) {
            int idx = tid + i * 256;
            int r = idx >> 3, u = idx & 7;
            const __nv_bfloat16* src = Ab + (size_t)r * 2 * K +
                ((u < 4) ? (k0 + u * 8) : (K + k0 + (u - 4) * 8));
            CP_ASYNC16(sa + swz((r << 7) | (u << 4)), (const char*)src);
        }
        uint32_t sb = sa + A_BYTES;
        #pragma unroll
        for (int i = 0; i < (BN * 8 + 255) / 256; i++) {
            int idx = tid + i * 256;
            if (BN * 8 % 256 == 0 || idx < BN * 8) {
                int r = idx >> 3, u = idx & 7;
                const __nv_bfloat16* src = Bb + (size_t)r * 2 * K +
                    ((u < 4) ? (k0 + u * 8) : (K + k0 + (u - 4) * 8));
                CP_ASYNC16(sb + swz((r << 7) | (u << 4)), (const char*)src);
            }
        }
    };

    float acc[MF][NF][4];
    #pragma unroll
    for (int i = 0; i < MF; i++)
        #pragma unroll
        for (int j = 0; j < NF; j++)
            #pragma unroll
            for (int e = 0; e < 4; e++) acc[i][j][e] = 0.0f;

    load_chunk(0, 0); CP_COMMIT();
    if (nch > 1) load_chunk(1, 1);
    CP_COMMIT();

    int a_mi = lane >> 3, a_r = lane & 7;
    int b_grp = lane >> 3, b_r = lane & 7;

    for (int c = 0; c < nch; c++) {
        CP_WAIT1();
        __syncthreads();
        if (c + 2 < nch) load_chunk(c + 2, (c + 2) % NSTG);
        CP_COMMIT();

        int s = c % NSTG;
        uint32_t sa = smb + s * STAGE;
        uint32_t sb = sa + A_BYTES;
        #pragma unroll
        for (int ksi = 0; ksi < 2; ksi++) {
            uint32_t afh[MF][4];
            #pragma unroll
            for (int mf = 0; mf < MF; mf++) {
                int row = wm * 32 + mf * 16 + ((a_mi & 1) << 3) + a_r;
                ldm_x4(afh[mf], sa + swz((row << 7) | ((ksi * 2 + (a_mi >> 1)) << 4)));
            }
            #pragma unroll
            for (int nfp = 0; nfp < NF / 2; nfp++) {
                uint32_t bfr[4];
                int row = wn * WN + (nfp * 2 + (b_grp >> 1)) * 8 + b_r;
                ldm_x4(bfr, sb + swz((row << 7) | ((ksi * 2 + (b_grp & 1)) << 4)));
                #pragma unroll
                for (int mf = 0; mf < MF; mf++) {
                    mma_bf16(acc[mf][nfp * 2 + 0], afh[mf], bfr);
                    mma_bf16(acc[mf][nfp * 2 + 1], afh[mf], bfr + 2);
                }
            }
            #pragma unroll
            for (int nfp = 0; nfp < NF / 2; nfp++) {
                uint32_t bfr[4];
                int row = wn * WN + (nfp * 2 + (b_grp >> 1)) * 8 + b_r;
                ldm_x4(bfr, sb + swz((row << 7) | ((4 + ksi * 2 + (b_grp & 1)) << 4)));
                #pragma unroll
                for (int mf = 0; mf < MF; mf++) {
                    mma_bf16(acc[mf][nfp * 2 + 0], afh[mf], bfr);
                    mma_bf16(acc[mf][nfp * 2 + 1], afh[mf], bfr + 2);
                }
            }
            uint32_t afl[MF][4];
            #pragma unroll
            for (int mf = 0; mf < MF; mf++) {
                int row = wm * 32 + mf * 16 + ((a_mi & 1) << 3) + a_r;
                ldm_x4(afl[mf], sa + swz((row << 7) | ((4 + ksi * 2 + (a_mi >> 1)) << 4)));
            }
            #pragma unroll
            for (int nfp = 0; nfp < NF / 2; nfp++) {
                uint32_t bfr[4];
                int row = wn * WN + (nfp * 2 + (b_grp >> 1)) * 8 + b_r;
                ldm_x4(bfr, sb + swz((row << 7) | ((ksi * 2 + (b_grp & 1)) << 4)));
                #pragma unroll
                for (int mf = 0; mf < MF; mf++) {
                    mma_bf16(acc[mf][nfp * 2 + 0], afl[mf], bfr);
                    mma_bf16(acc[mf][nfp * 2 + 1], afl[mf], bfr + 2);
                }
            }
        }
    }

    int cr = lane >> 2, cc2 = (lane & 3) << 1;
    #pragma unroll
    for (int mf = 0; mf < MF; mf++) {
        #pragma unroll
        for (int half = 0; half < 2; half++) {
            int gm = bm + wm * 32 + mf * 16 + cr + half * 8;
            #pragma unroll
            for (int nf = 0; nf < NF; nf++) {
                int gn = bn + wn * WN + nf * 8 + cc2;
                float v0 = acc[mf][nf][half * 2 + 0];
                float v1 = acc[mf][nf][half * 2 + 1];
                if (bias) { v0 += __ldg(&bias[gn]); v1 += __ldg(&bias[gn + 1]); }
                if (GELU) { v0 = gelu_f(v0); v1 = gelu_f(v1); }
                if (MODE == 1) {
                    __nv_bfloat162 hp, lp;
                    split2(v0, v1, hp, lp);
                    __nv_bfloat16* row = Cx2 + (size_t)gm * (2 * N);
                    *(__nv_bfloat162*)(row + gn) = hp;
                    *(__nv_bfloat162*)(row + N + gn) = lp;
                } else if (MODE == 2) {
                    int b = gm / NN, n = gm - b * NN;
                    int part = gn / CC, w = gn - part * CC;
                    int h = w >> 6, d = w & 63;
                    int tile = n >> 6, r = n & 63;
                    int bh = b * HH + h;
                    __nv_bfloat162 hp, lp;
                    split2(v0, v1, hp, lp);
                    size_t sbase = ((size_t)(bh * 4 + tile)) * 2 * 4096;
                    if (part == 0) {
                        *(__nv_bfloat162*)(qs + sbase + r * 64 + d) = hp;
                        *(__nv_bfloat162*)(qs + sbase + 4096 + r * 64 + d) = lp;
                    } else if (part == 1) {
                        *(__nv_bfloat162*)(ks_ + sbase + r * 64 + d) = hp;
                        *(__nv_bfloat162*)(ks_ + sbase + 4096 + r * 64 + d) = lp;
                    } else {
                        vt[sbase + d * 64 + r] = hp.x;
                        vt[sbase + (d + 1) * 64 + r] = hp.y;
                        vt[sbase + 4096 + d * 64 + r] = lp.x;
                        vt[sbase + 4096 + (d + 1) * 64 + r] = lp.y;
                    }
                } else {
                    if (RES) {
                        float2 rv = *(const float2*)(res + (size_t)gm * N + gn);
                        v0 += rv.x; v1 += rv.y;
                    }
                    *(float2*)(C + (size_t)gm * N + gn) = make_float2(v0, v1);
                }
            }
        }
    }
}

// ================= fused QK + softmax + P-split, 256 threads =================
// 8 warps: m-stripe = wid&3 (16 rows), k-half = wid>>2 (2 k-tiles of 64).
// Q + all 4 K tiles loaded in one cp.async batch (80KB smem).
__global__ void __launch_bounds__(256)
attn_qks(const __nv_bfloat16* __restrict__ Qs, const __nv_bfloat16* __restrict__ Ks,
         __nv_bfloat16* __restrict__ Ps) {
    extern __shared__ __align__(128) char smdyn[];
    uint32_t smb = smem_u32(smdyn);
    uint32_t smQ = smb, smK = smb + 16384;
    __shared__ float redmx[2][64], redsum[2][64];
    int qt = blockIdx.x, bh = blockIdx.y;
    int tid = threadIdx.x, wid = tid >> 5, lane = tid & 31;
    int wm = wid & 3, g = wid >> 2;
    int a_mi = lane >> 3, a_r = lane & 7, b_grp = lane >> 3, b_r = lane & 7;

    const char* Qb = (const char*)(Qs + ((size_t)(bh * 4 + qt)) * 2 * 4096);
    const char* Kb = (const char*)(Ks + ((size_t)(bh * 4)) * 2 * 4096);  // 4 tiles contiguous
    for (int c = tid; c < 1024; c += 256) {
        int slab = c >> 9, rem = c & 511, row = rem >> 3, unit = rem & 7;
        CP_ASYNC16(smQ + slab * 8192 + swz((row << 7) | (unit << 4)), Qb + (size_t)c * 16);
    }
    for (int c = tid; c < 4096; c += 256) {
        int tile = c >> 10, rem1 = c & 1023;
        int slab = rem1 >> 9, rem = rem1 & 511, row = rem >> 3, unit = rem & 7;
        CP_ASYNC16(smK + tile * 16384 + slab * 8192 + swz((row << 7) | (unit << 4)),
                   Kb + (size_t)c * 16);
    }
    CP_COMMIT(); CP_WAIT0();
    __syncthreads();

    float acc[2][8][4];
    #pragma unroll
    for (int kti = 0; kti < 2; kti++)
        #pragma unroll
        for (int nf = 0; nf < 8; nf++)
            #pragma unroll
            for (int e = 0; e < 4; e++) acc[kti][nf][e] = 0.f;

    const int pa[3] = {0, 0, 1}, pb[3] = {0, 1, 0};
    #pragma unroll
    for (int kti = 0; kti < 2; kti++) {
        uint32_t smKt = smK + (g * 2 + kti) * 16384;
        #pragma unroll
        for (int p = 0; p < 3; p++) {
            #pragma unroll
            for (int ksi = 0; ksi < 4; ksi++) {
                uint32_t afr[4];
                int arow = wm * 16 + ((a_mi & 1) << 3) + a_r;
                ldm_x4(afr, smQ + pa[p] * 8192 + swz((arow << 7) | ((ksi * 2 + (a_mi >> 1)) << 4)));
                #pragma unroll
                for (int nfp = 0; nfp < 4; nfp++) {
                    uint32_t bfr[4];
                    int brow = (nfp * 2 + (b_grp >> 1)) * 8 + b_r;
                    ldm_x4(bfr, smKt + pb[p] * 8192 + swz((brow << 7) | ((ksi * 2 + (b_grp & 1)) << 4)));
                    mma_bf16(acc[kti][nfp * 2 + 0], afr, bfr);
                    mma_bf16(acc[kti][nfp * 2 + 1], afr, bfr + 2);
                }
            }
        }
    }

    int cr = lane >> 2, cc2 = (lane & 3) << 1;
    int r0 = wm * 16 + cr, r1 = r0 + 8;
    // scale + mask
    #pragma unroll
    for (int kti = 0; kti < 2; kti++)
        #pragma unroll
        for (int nf = 0; nf < 8; nf++)
            #pragma unroll
            for (int e = 0; e < 4; e++) {
                int k = (g * 2 + kti) * 64 + nf * 8 + cc2 + (e & 1);
                float s = acc[kti][nf][e] * 0.125f;
                acc[kti][nf][e] = (k < NN) ? s : -INFINITY;
            }
    // local max over this k-half
    float mx0 = -INFINITY, mx1 = -INFINITY;
    #pragma unroll
    for (int kti = 0; kti < 2; kti++)
        #pragma unroll
        for (int nf = 0; nf < 8; nf++) {
            mx0 = fmaxf(mx0, fmaxf(acc[kti][nf][0], acc[kti][nf][1]));
            mx1 = fmaxf(mx1, fmaxf(acc[kti][nf][2], acc[kti][nf][3]));
        }
    #pragma unroll
    for (int o = 1; o <= 2; o <<= 1) {
        mx0 = fmaxf(mx0, __shfl_xor_sync(0xffffffff, mx0, o));
        mx1 = fmaxf(mx1, __shfl_xor_sync(0xffffffff, mx1, o));
    }
    if ((lane & 3) == 0) { redmx[g][r0] = mx0; redmx[g][r1] = mx1; }
    __syncthreads();
    mx0 = fmaxf(mx0, redmx[1 ^ g][r0]);
    mx1 = fmaxf(mx1, redmx[1 ^ g][r1]);
    // exp + local sum
    float s0 = 0.f, s1 = 0.f;
    #pragma unroll
    for (int kti = 0; kti < 2; kti++)
        #pragma unroll
        for (int nf = 0; nf < 8; nf++) {
            float e0 = __expf(acc[kti][nf][0] - mx0);
            float e1 = __expf(acc[kti][nf][1] - mx0);
            float e2 = __expf(acc[kti][nf][2] - mx1);
            float e3 = __expf(acc[kti][nf][3] - mx1);
            acc[kti][nf][0] = e0; acc[kti][nf][1] = e1;
            acc[kti][nf][2] = e2; acc[kti][nf][3] = e3;
            s0 += e0 + e1; s1 += e2 + e3;
        }
    #pragma unroll
    for (int o = 1; o <= 2; o <<= 1) {
        s0 += __shfl_xor_sync(0xffffffff, s0, o);
        s1 += __shfl_xor_sync(0xffffffff, s1, o);
    }
    if ((lane & 3) == 0) { redsum[g][r0] = s0; redsum[g][r1] = s1; }
    __syncthreads();
    s0 += redsum[1 ^ g][r0];
    s1 += redsum[1 ^ g][r1];
    float inv0 = 1.0f / s0, inv1 = 1.0f / s1;

    __nv_bfloat16* base = Ps + ((size_t)(bh * 4 + qt) * 4) * 2 * 4096;
    #pragma unroll
    for (int kti = 0; kti < 2; kti++) {
        int kt = g * 2 + kti;
        #pragma unroll
        for (int nf = 0; nf < 8; nf++) {
            int col = nf * 8 + cc2;
            __nv_bfloat162 hp, lp;
            split2(acc[kti][nf][0] * inv0, acc[kti][nf][1] * inv0, hp, lp);
            size_t off = (size_t)kt * 2 * 4096 + r0 * 64 + col;
            *(__nv_bfloat162*)(base + off) = hp;
            *(__nv_bfloat162*)(base + off + 4096) = lp;
            split2(acc[kti][nf][2] * inv1, acc[kti][nf][3] * inv1, hp, lp);
            off = (size_t)kt * 2 * 4096 + r1 * 64 + col;
            *(__nv_bfloat162*)(base + off) = hp;
            *(__nv_bfloat162*)(base + off + 4096) = lp;
        }
    }
}

// ================= AV: 256 threads, double-buffered (P,V) pipeline =================
// 8 warps: m-stripe = wid&3, n-half = wid>>2 (32 cols each).
__global__ void __launch_bounds__(256)
attn_av(const __nv_bfloat16* __restrict__ Ps, const __nv_bfloat16* __restrict__ Vt,
        __nv_bfloat16* __restrict__ Ox2) {
    extern __shared__ __align__(128) char smdyn[];
    uint32_t smb = smem_u32(smdyn);
    int qt = blockIdx.x, bh = blockIdx.y;
    int b = bh / HH, h = bh % HH;
    int tid = threadIdx.x, wid = tid >> 5, lane = tid & 31;
    int wm = wid & 3, wh = wid >> 2;
    int a_mi = lane >> 3, a_r = lane & 7, b_grp = lane >> 3, b_r = lane & 7;
    float acc[4][4];
    #pragma unroll
    for (int i = 0; i < 4; i++)
        #pragma unroll
        for (int e = 0; e < 4; e++) acc[i][e] = 0.f;

    const char* Pb0 = (const char*)(Ps + ((size_t)((bh * 4 + qt) * 4)) * 2 * 4096);
    const char* Vb0 = (const char*)(Vt + ((size_t)(bh * 4)) * 2 * 4096);
    auto load_kt = [&](int kt, int s) {
        uint32_t smP = smb + s * 32768;
        uint32_t smV = smP + 16384;
        const char* Pb = Pb0 + (size_t)kt * 16384;
        const char* Vb = Vb0 + (size_t)kt * 16384;
        #pragma unroll
        for (int i = 0; i < 4; i++) {
            int c = tid + i * 256;
            int slab = c >> 9, rem = c & 511, row = rem >> 3, unit = rem & 7;
            uint32_t off = slab * 8192 + swz((row << 7) | (unit << 4));
            CP_ASYNC16(smP + off, Pb + (size_t)c * 16);
            CP_ASYNC16(smV + off, Vb + (size_t)c * 16);
        }
    };

    load_kt(0, 0); CP_COMMIT();
    load_kt(1, 1); CP_COMMIT();

    const int pa[3] = {0, 0, 1}, pb[3] = {0, 1, 0};
    for (int kt = 0; kt < 4; kt++) {
        if (kt == 3) { CP_WAIT0(); } else { CP_WAIT1(); }
        __syncthreads();
        uint32_t smP = smb + (kt & 1) * 32768;
        uint32_t smV = smP + 16384;
        #pragma unroll
        for (int p = 0; p < 3; p++) {
            #pragma unroll
            for (int ksi = 0; ksi < 4; ksi++) {
                uint32_t afr[4];
                int arow = wm * 16 + ((a_mi & 1) << 3) + a_r;
                ldm_x4(afr, smP + pa[p] * 8192 + swz((arow << 7) | ((ksi * 2 + (a_mi >> 1)) << 4)));
                #pragma unroll
                for (int nfp = 0; nfp < 2; nfp++) {
                    uint32_t bfr[4];
                    int brow = wh * 32 + (nfp * 2 + (b_grp >> 1)) * 8 + b_r;
                    ldm_x4(bfr, smV + pb[p] * 8192 + swz((brow << 7) | ((ksi * 2 + (b_grp & 1)) << 4)));
                    mma_bf16(acc[nfp * 2 + 0], afr, bfr);
                    mma_bf16(acc[nfp * 2 + 1], afr, bfr + 2);
                }
            }
        }
        __syncthreads();
        if (kt + 2 < 4) { load_kt(kt + 2, kt & 1); }
        CP_COMMIT();
    }
    int cr = lane >> 2, cc2 = (lane & 3) << 1;
    #pragma unroll
    for (int nf = 0; nf < 4; nf++) {
        #pragma unroll
        for (int half = 0; half < 2; half++) {
            int q = qt * 64 + wm * 16 + cr + half * 8;
            if (q < NN) {
                int m = b * NN + q;
                int col = h * HD + wh * 32 + nf * 8 + cc2;
                __nv_bfloat162 hp, lp;
                split2(acc[nf][half * 2 + 0], acc[nf][half * 2 + 1], hp, lp);
                __nv_bfloat16* row = Ox2 + (size_t)m * (2 * CC);
                *(__nv_bfloat162*)(row + col) = hp;
                *(__nv_bfloat162*)(row + CC + col) = lp;
            }
        }
    }
}

// ---------------- LayerNorm D=768 -> [hi|lo] ----------------
__global__ void ln768_x2(const float* __restrict__ x, const float* __restrict__ g,
                         const float* __restrict__ b, __nv_bfloat16* __restrict__ out) {
    int row = blockIdx.x;
    const float* p = x + (size_t)row * CC;
    int tid = threadIdx.x;
    float v0 = p[tid], v1 = p[tid + 256], v2 = p[tid + 512];
    float s = v0 + v1 + v2;
    float sq = v0 * v0 + v1 * v1 + v2 * v2;
    __shared__ float rs[256], rq[256];
    rs[tid] = s; rq[tid] = sq; __syncthreads();
    for (int st = 128; st > 0; st >>= 1) {
        if (tid < st) { rs[tid] += rs[tid + st]; rq[tid] += rq[tid + st]; }
        __syncthreads();
    }
    float mean = rs[0] * (1.0f / CC);
    float var  = rq[0] * (1.0f / CC) - mean * mean;
    float inv = rsqrtf(var + 1e-5f);
    __nv_bfloat16* o = out + (size_t)row * (2 * CC);
    #pragma unroll
    for (int j = 0; j < 3; j++) {
        int c = tid + j * 256;
        float y = (p[c] - mean) * inv * g[c] + b[c];
        __nv_bfloat16 hi = __float2bfloat16(y);
        o[c] = hi;
        o[CC + c] = __float2bfloat16(y - __bfloat162float(hi));
    }
}

// ---------------- LayerNorm D=32 ----------------
__global__ void ln32_kernel(const float* __restrict__ x, const float* __restrict__ g,
                            const float* __restrict__ b, float* __restrict__ out) {
    int row = blockIdx.x * 8 + threadIdx.x / 32;
    int lane = threadIdx.x & 31;
    float v = x[(size_t)row * OUTC + lane];
    float s = v, sq = v * v;
    #pragma unroll
    for (int o = 16; o > 0; o >>= 1) {
        s  += __shfl_xor_sync(0xffffffff, s, o);
        sq += __shfl_xor_sync(0xffffffff, sq, o);
    }
    float mean = s * (1.0f / OUTC);
    float var  = sq * (1.0f / OUTC) - mean * mean;
    float inv = rsqrtf(var + 1e-5f);
    out[(size_t)row * OUTC + lane] = (v - mean) * inv * g[lane] + b[lane];
}

// ---------------- fp32 SIMT GEMM (small channel GEMMs) ----------------
template<int BM, int BN, int BK, int TM, int TN, bool GELU, bool RES>
__global__ void gemm_nt(const float* __restrict__ A, const float* __restrict__ Bw,
                        const float* __restrict__ bias, const float* __restrict__ res,
                        float* __restrict__ C, int M, int N, int K) {
    constexpr int THREADS = (BM / TM) * (BN / TN);
    __shared__ float As[BK][BM];
    __shared__ float Bs[BK][BN];
    int tid = threadIdx.x;
    int bm = blockIdx.y * BM, bn = blockIdx.x * BN;
    int tx = tid % (BN / TN), ty = tid / (BN / TN);
    float acc[TM][TN];
    #pragma unroll
    for (int i = 0; i < TM; i++)
        #pragma unroll
        for (int j = 0; j < TN; j++) acc[i][j] = 0.0f;
    constexpr int A4 = BM * BK / 4;
    constexpr int B4 = BN * BK / 4;
    for (int k0 = 0; k0 < K; k0 += BK) {
        #pragma unroll
        for (int i = tid; i < A4; i += THREADS) {
            int row = i / (BK / 4);
            int kk  = (i % (BK / 4)) * 4;
            float4 v = make_float4(0.f, 0.f, 0.f, 0.f);
            if (k0 + kk < K) v = *(const float4*)(A + (size_t)(bm + row) * K + k0 + kk);
            As[kk + 0][row] = v.x; As[kk + 1][row] = v.y;
            As[kk + 2][row] = v.z; As[kk + 3][row] = v.w;
        }
        #pragma unroll
        for (int i = tid; i < B4; i += THREADS) {
            int row = i / (BK / 4);
            int kk  = (i % (BK / 4)) * 4;
            float4 v = make_float4(0.f, 0.f, 0.f, 0.f);
            if (bn + row < N && k0 + kk < K)
                v = *(const float4*)(Bw + (size_t)(bn + row) * K + k0 + kk);
            Bs[kk + 0][row] = v.x; Bs[kk + 1][row] = v.y;
            Bs[kk + 2][row] = v.z; Bs[kk + 3][row] = v.w;
        }
        __syncthreads();
        #pragma unroll
        for (int kk = 0; kk < BK; kk++) {
            float a[TM], bv[TN];
            #pragma unroll
            for (int i = 0; i < TM; i++) a[i] = As[kk][ty * TM + i];
            #pragma unroll
            for (int j = 0; j < TN; j++) bv[j] = Bs[kk][tx * TN + j];
            #pragma unroll
            for (int i = 0; i < TM; i++)
                #pragma unroll
                for (int j = 0; j < TN; j++) acc[i][j] += a[i] * bv[j];
        }
        __syncthreads();
    }
    #pragma unroll
    for (int i = 0; i < TM; i++) {
        int gm = bm + ty * TM + i;
        #pragma unroll
        for (int j = 0; j < TN; j++) {
            int gn = bn + tx * TN + j;
            if (gn < N) {
                float v = acc[i][j];
                if (bias) v += bias[gn];
                if (GELU) v = gelu_f(v);
                if (RES) v += res[(size_t)gm * N + gn];
                C[(size_t)gm * N + gn] = v;
            }
        }
    }
}

// ---------------- t[b,c,s] = ln3[b, 1+s, c] ----------------
__global__ void make_t_kernel(const float* __restrict__ ln3, float* __restrict__ t) {
    int idx = blockIdx.x * 256 + threadIdx.x;
    if (idx >= BB * OUTC * CNN) return;
    int s = idx % CNN;
    int c = (idx / CNN) % OUTC;
    int b = idx / (CNN * OUTC);
    t[idx] = ln3[((size_t)(b * NN + 1 + s)) * OUTC + c];
}

// ---------------- tiny channel attention ----------------
__global__ void chattn_kernel(const float* __restrict__ cqkv, float* __restrict__ co) {
    int b = blockIdx.x / CHH, h = blockIdx.x % CHH;
    int tid = threadIdx.x;
    __shared__ float Q[OUTC][CHD], Kk[OUTC][CHD], V[OUTC][CHD], S[OUTC][OUTC + 1];
    const float* base = cqkv + (size_t)b * OUTC * (3 * CNN);
    for (int i = tid; i < OUTC * CHD; i += 256) {
        int r = i / CHD, d = i % CHD;
        Q[r][d]  = base[r * (3 * CNN) + h * CHD + d];
        Kk[r][d] = base[r * (3 * CNN) + CNN + h * CHD + d];
        V[r][d]  = base[r * (3 * CNN) + 2 * CNN + h * CHD + d];
    }
    __syncthreads();
    const float sc = rsqrtf((float)CHD);
    for (int i = tid; i < OUTC * OUTC; i += 256) {
        int qi = i / OUTC, kj = i % OUTC;
        float s = 0.0f;
        #pragma unroll
        for (int d = 0; d < CHD; d++) s += Q[qi][d] * Kk[kj][d];
        S[qi][kj] = s * sc;
    }
    __syncthreads();
    if (tid < OUTC) {
        float mx = -INFINITY;
        #pragma unroll
        for (int j = 0; j < OUTC; j++) mx = fmaxf(mx, S[tid][j]);
        float sum = 0.0f;
        #pragma unroll
        for (int j = 0; j < OUTC; j++) { float e = __expf(S[tid][j] - mx); S[tid][j] = e; sum += e; }
        float inv = 1.0f / sum;
        #pragma unroll
        for (int j = 0; j < OUTC; j++) S[tid][j] *= inv;
    }
    __syncthreads();
    for (int i = tid; i < OUTC * CHD; i += 256) {
        int qi = i / CHD, d = i % CHD;
        float s = 0.0f;
        #pragma unroll
        for (int kk = 0; kk < OUTC; kk++) s += S[qi][kk] * V[kk][d];
        co[((size_t)(b * OUTC + qi)) * CNN + h * CHD + d] = s;
    }
}

// ---------------- x32 += concat([ln3 cls, co2^T]) ----------------
__global__ void concat_add_kernel(const float* __restrict__ ln3, const float* __restrict__ co2,
                                  float* __restrict__ x32) {
    int idx = blockIdx.x * 256 + threadIdx.x;
    if (idx >= MROWS * OUTC) return;
    int c = idx % OUTC;
    int n = (idx / OUTC) % NN;
    int b = idx / (OUTC * NN);
    float add;
    if (n == 0) add = ln3[((size_t)b * NN) * OUTC + c];
    else        add = co2[((size_t)(b * OUTC + c)) * CNN + (n - 1)];
    x32[idx] += add;
}

// ---------------- launch ----------------
static inline int cdiv(long long a, int b) { return (int)((a + b - 1) / b); }

extern "C" void kernel_launch(void* const* d_in, const int* in_sizes, int n_in,
                              void* d_out, int out_size) {
    const float* x      = (const float*)d_in[0];
    const float* g1     = (const float*)d_in[1];
    const float* b1     = (const float*)d_in[2];
    const float* w_qkv  = (const float*)d_in[3];
    const float* w_proj = (const float*)d_in[4];
    const float* b_proj = (const float*)d_in[5];
    const float* g2     = (const float*)d_in[6];
    const float* b2     = (const float*)d_in[7];
    const float* w_fc1  = (const float*)d_in[8];
    const float* b_fc1  = (const float*)d_in[9];
    const float* w_fc2  = (const float*)d_in[10];
    const float* b_fc2  = (const float*)d_in[11];
    const float* g3     = (const float*)d_in[12];
    const float* b3     = (const float*)d_in[13];
    const float* w_cqkv = (const float*)d_in[14];
    const float* w_cproj= (const float*)d_in[15];
    const float* b_cproj= (const float*)d_in[16];
    const float* g4     = (const float*)d_in[17];
    const float* b4     = (const float*)d_in[18];
    const float* w_cfc1 = (const float*)d_in[19];
    const float* b_cfc1 = (const float*)d_in[20];
    const float* w_cfc2 = (const float*)d_in[21];
    const float* b_cfc2 = (const float*)d_in[22];
    float* out = (float*)d_out;

    float *p_x, *p_x32, *p_ln32, *p_t, *p_cqkv, *p_co, *p_co2, *p_cmlp;
    __nv_bfloat16 *p_abf, *p_abf2, *p_wbf, *p_qs, *p_ks, *p_vt, *p_ps;
    cudaGetSymbolAddress((void**)&p_x,    g_x);
    cudaGetSymbolAddress((void**)&p_x32,  g_x32);
    cudaGetSymbolAddress((void**)&p_ln32, g_ln32);
    cudaGetSymbolAddress((void**)&p_t,    g_t);
    cudaGetSymbolAddress((void**)&p_cqkv, g_cqkv);
    cudaGetSymbolAddress((void**)&p_co,   g_co);
    cudaGetSymbolAddress((void**)&p_co2,  g_co2);
    cudaGetSymbolAddress((void**)&p_cmlp, g_cmlp);
    cudaGetSymbolAddress((void**)&p_abf,  g_abf);
    cudaGetSymbolAddress((void**)&p_abf2, g_abf2);
    cudaGetSymbolAddress((void**)&p_wbf,  g_wbf);
    cudaGetSymbolAddress((void**)&p_qs,   g_qs);
    cudaGetSymbolAddress((void**)&p_ks,   g_ks);
    cudaGetSymbolAddress((void**)&p_vt,   g_vt);
    cudaGetSymbolAddress((void**)&p_ps,   g_ps);

    const int SM128 = 3 * (128 * 128 + 128 * 128) + 1024;
    const int SM32  = 3 * (128 * 128 + 32 * 128) + 1024;
    const int SMQKS = 16384 + 4 * 16384;   // 81920
    const int SMAV  = 2 * 32768;           // 65536
    cudaFuncSetAttribute(gemm_mma<128, false, false, 2>, cudaFuncAttributeMaxDynamicSharedMemorySize, SM128);
    cudaFuncSetAttribute(gemm_mma<128, false, true,  0>, cudaFuncAttributeMaxDynamicSharedMemorySize, SM128);
    cudaFuncSetAttribute(gemm_mma<128, true,  false, 1>, cudaFuncAttributeMaxDynamicSharedMemorySize, SM128);
    cudaFuncSetAttribute(gemm_mma<32,  false, false, 0>, cudaFuncAttributeMaxDynamicSharedMemorySize, SM32);
    cudaFuncSetAttribute(gemm_mma<32,  false, true,  0>, cudaFuncAttributeMaxDynamicSharedMemorySize, SM32);
    cudaFuncSetAttribute(attn_qks, cudaFuncAttributeMaxDynamicSharedMemorySize, SMQKS);
    cudaFuncSetAttribute(attn_av,  cudaFuncAttributeMaxDynamicSharedMemorySize, SMAV);

    const int M = MROWS;
    const int MB = M / 128;

    // 1. LN1 -> [hi|lo]
    ln768_x2<<<M, 256>>>(x, g1, b1, p_abf);
    // 2. qkv GEMM, epilogue writes Q/K/V slabs directly
    conv_x2<<<cdiv((long long)3 * CC * CC / 4, 256), 256>>>(w_qkv, p_wbf, 3 * CC, CC);
    gemm_mma<128, false, false, 2><<<dim3(18, MB), 256, SM128>>>(
        p_abf, p_wbf, nullptr, nullptr, nullptr, nullptr, p_qs, p_ks, p_vt, M, 3 * CC, CC);
    // 3. fused QK+softmax+split, then AV
    attn_qks<<<dim3(4, NBH), 256, SMQKS>>>(p_qs, p_ks, p_ps);
    attn_av<<<dim3(4, NBH), 256, SMAV>>>(p_ps, p_vt, p_abf);
    // 4. x = x_in + O @ w_proj^T + b_proj
    conv_x2<<<cdiv((long long)CC * CC / 4, 256), 256>>>(w_proj, p_wbf, CC, CC);
    gemm_mma<128, false, true, 0><<<dim3(6, MB), 256, SM128>>>(
        p_abf, p_wbf, b_proj, x, p_x, nullptr, nullptr, nullptr, nullptr, M, CC, CC);
    // 5. LN2 -> [hi|lo]
    ln768_x2<<<M, 256>>>(p_x, g2, b2, p_abf);
    // 6. hidden = gelu(...) -> [hi|lo]
    conv_x2<<<cdiv((long long)MLPH * CC / 4, 256), 256>>>(w_fc1, p_wbf, MLPH, CC);
    gemm_mma<128, true, false, 1><<<dim3(24, MB), 256, SM128>>>(
        p_abf, p_wbf, b_fc1, nullptr, nullptr, p_abf2, nullptr, nullptr, nullptr, M, MLPH, CC);
    // 7. x32 = hidden @ w_fc2^T + b_fc2
    conv_x2<<<cdiv((long long)OUTC * MLPH / 4, 256), 256>>>(w_fc2, p_wbf, OUTC, MLPH);
    gemm_mma<32, false, false, 0><<<dim3(1, MB), 256, SM32>>>(
        p_abf2, p_wbf, b_fc2, nullptr, p_x32, nullptr, nullptr, nullptr, nullptr, M, OUTC, MLPH);
    // 8. LN3
    ln32_kernel<<<M / 8, 256>>>(p_x32, g3, b3, p_ln32);
    // 9. channel branch
    make_t_kernel<<<(BB * OUTC * CNN + 255) / 256, 256>>>(p_ln32, p_t);
    gemm_nt<128, 128, 16, 8, 8, false, false><<<dim3(5, CMROWS / 128), 256>>>(p_t, w_cqkv, nullptr, nullptr, p_cqkv, CMROWS, 3 * CNN, CNN);
    chattn_kernel<<<BB * CHH, 256>>>(p_cqkv, p_co);
    gemm_nt<128, 128, 16, 8, 8, false, false><<<dim3(2, CMROWS / 128), 256>>>(p_co, w_cproj, b_cproj, nullptr, p_co2, CMROWS, CNN, CNN);
    concat_add_kernel<<<(M * OUTC + 255) / 256, 256>>>(p_ln32, p_co2, p_x32);
    // 10. LN4 + channel MLP
    ln32_kernel<<<M / 8, 256>>>(p_x32, g4, b4, p_ln32);
    gemm_nt<128, 128, 16, 8, 8, true, false><<<dim3(1, MB), 256>>>(p_ln32, w_cfc1, b_cfc1, nullptr, p_cmlp, M, CMLPH, OUTC);
    conv_x2<<<cdiv((long long)M * CMLPH / 4, 256), 256>>>(p_cmlp, p_abf, M, CMLPH);
    conv_x2<<<cdiv((long long)OUTC * CMLPH / 4, 256), 256>>>(w_cfc2, p_wbf, OUTC, CMLPH);
    gemm_mma<32, false, true, 0><<<dim3(1, MB), 256, SM32>>>(
        p_abf, p_wbf, b_cfc2, p_x32, out, nullptr, nullptr, nullptr, nullptr, M, OUTC, CMLPH);
}

// round 11
// speedup vs baseline: 1.0715x; 1.0397x over previous
#include <cuda_runtime.h>
#include <cuda_bf16.h>
#include <math.h>
#include <stdint.h>
#include <stddef.h>

#define BB   128
#define NN   197
#define CC   768
#define HH   12
#define HD   64
#define OUTC 32
#define CHH  14
#define CHD  14
#define CNN  196
#define MLPH 3072
#define CMLPH 128
#define MROWS (BB*NN)          // 25216
#define CMROWS (BB*OUTC)       // 4096
#define NBH   (BB*HH)          // 1536

// ---------------- scratch ----------------
__device__ float g_x   [MROWS*CC];
__device__ float g_x32 [MROWS*OUTC];
__device__ float g_ln32[MROWS*OUTC];
__device__ float g_t   [BB*OUTC*CNN];
__device__ float g_cqkv[BB*OUTC*3*CNN];
__device__ float g_co  [BB*OUTC*CNN];
__device__ float g_co2 [BB*OUTC*CNN];
__device__ float g_cmlp[MROWS*CMLPH];
__device__ __nv_bfloat16 g_abf [(size_t)MROWS*2*CC];
__device__ __nv_bfloat16 g_abf2[(size_t)MROWS*2*MLPH];
__device__ __nv_bfloat16 g_wbf [(size_t)MLPH*2*CC];
__device__ __nv_bfloat16 g_qs  [(size_t)NBH*4*2*4096];
__device__ __nv_bfloat16 g_ks  [(size_t)NBH*4*2*4096];
__device__ __nv_bfloat16 g_vt  [(size_t)NBH*4*2*4096];

__device__ __forceinline__ float gelu_f(float x) {
    return 0.5f * x * (1.0f + erff(x * 0.70710678118654752440f));
}

// ================= PTX helpers =================
__device__ __forceinline__ uint32_t smem_u32(const void* p) {
    uint32_t a;
    asm("{ .reg .u64 t; cvta.to.shared.u64 t, %1; cvt.u32.u64 %0, t; }" : "=r"(a) : "l"(p));
    return a;
}
#define CP_ASYNC16(d, s)    asm volatile("cp.async.cg.shared.global [%0], [%1], 16;" :: "r"(d), "l"(s))
#define CP_COMMIT()         asm volatile("cp.async.commit_group;" ::: "memory")
#define CP_WAIT1()          asm volatile("cp.async.wait_group 1;" ::: "memory")
#define CP_WAIT0()          asm volatile("cp.async.wait_group 0;" ::: "memory")

__device__ __forceinline__ void ldm_x4(uint32_t* r, uint32_t addr) {
    asm volatile("ldmatrix.sync.aligned.m8n8.x4.shared.b16 {%0,%1,%2,%3}, [%4];"
        : "=r"(r[0]), "=r"(r[1]), "=r"(r[2]), "=r"(r[3]) : "r"(addr));
}
__device__ __forceinline__ void mma_bf16(float* c, const uint32_t* a, const uint32_t* b) {
    asm volatile("mma.sync.aligned.m16n8k16.row.col.f32.bf16.bf16.f32 "
        "{%0,%1,%2,%3}, {%4,%5,%6,%7}, {%8,%9}, {%0,%1,%2,%3};"
        : "+f"(c[0]), "+f"(c[1]), "+f"(c[2]), "+f"(c[3])
        : "r"(a[0]), "r"(a[1]), "r"(a[2]), "r"(a[3]), "r"(b[0]), "r"(b[1]));
}
__device__ __forceinline__ uint32_t swz(uint32_t off) { return off ^ ((off >> 3) & 0x70); }
__device__ __forceinline__ void split2(float a, float b, __nv_bfloat162& hp, __nv_bfloat162& lp) {
    __nv_bfloat16 h0 = __float2bfloat16(a), h1 = __float2bfloat16(b);
    hp = __nv_bfloat162(h0, h1);
    lp = __nv_bfloat162(__float2bfloat16(a - __bfloat162float(h0)),
                        __float2bfloat16(b - __bfloat162float(h1)));
}

// ================= conversions =================
__global__ void conv_x2(const float* __restrict__ in, __nv_bfloat16* __restrict__ out,
                        int Mr, int K) {
    long long idx = (long long)blockIdx.x * 256 + threadIdx.x;
    long long tot = (long long)Mr * (K / 4);
    if (idx >= tot) return;
    int m = (int)(idx / (K / 4)), k = (int)(idx % (K / 4)) * 4;
    float4 v = *(const float4*)(in + (size_t)m * K + k);
    __nv_bfloat162 hp0, lp0, hp1, lp1;
    split2(v.x, v.y, hp0, lp0); split2(v.z, v.w, hp1, lp1);
    __nv_bfloat16* row = out + (size_t)m * 2 * K;
    *(__nv_bfloat162*)(row + k) = hp0;           *(__nv_bfloat162*)(row + k + 2) = hp1;
    *(__nv_bfloat162*)(row + K + k) = lp0;       *(__nv_bfloat162*)(row + K + k + 2) = lp1;
}

// ================= mma.sync bf16 NT GEMM, 2-slab storage, 3-pass chunks =================
// MODE: 0 = fp32 out (opt RES), 1 = [hi|lo] bf16 out, 2 = qkv slab scatter
template<int BN, bool GELU, bool RES, int MODE>
__global__ void __launch_bounds__(256, 2)
gemm_mma(const __nv_bfloat16* __restrict__ A, const __nv_bfloat16* __restrict__ Bw,
         const float* __restrict__ bias, const float* __restrict__ res,
         float* __restrict__ C, __nv_bfloat16* __restrict__ Cx2,
         __nv_bfloat16* __restrict__ qs, __nv_bfloat16* __restrict__ ks_,
         __nv_bfloat16* __restrict__ vt, int M, int N, int K) {
    constexpr int A_BYTES = 128 * 128;
    constexpr int B_BYTES = BN * 128;
    constexpr int STAGE = A_BYTES + B_BYTES;
    constexpr int NSTG = 3;
    constexpr int WN = BN / 2;
    constexpr int MF = 2;
    constexpr int NF = WN / 8;

    extern __shared__ char smraw[];
    char* sm = (char*)(((uintptr_t)smraw + 1023) & ~(uintptr_t)1023);
    uint32_t smb = smem_u32(sm);

    int tid = threadIdx.x, wid = tid >> 5, lane = tid & 31;
    int wm = wid & 3, wn = wid >> 2;
    int bm = blockIdx.y * 128, bn = blockIdx.x * BN;
    const __nv_bfloat16* Ab = A + (size_t)bm * 2 * K;
    const __nv_bfloat16* Bb = Bw + (size_t)bn * 2 * K;
    const int nch = K >> 5;

    auto load_chunk = [&](int c, int s) {
        int k0 = c << 5;
        uint32_t sa = smb + s * STAGE;
        #pragma unroll
        for (int i = 0; i < (128 * 8) / 256; i++) {
            int idx = tid + i * 256;
            int r = idx >> 3, u = idx & 7;
            const __nv_bfloat16* src = Ab + (size_t)r * 2 * K +
                ((u < 4) ? (k0 + u * 8) : (K + k0 + (u - 4) * 8));
            CP_ASYNC16(sa + swz((r << 7) | (u << 4)), (const char*)src);
        }
        uint32_t sb = sa + A_BYTES;
        #pragma unroll
        for (int i = 0; i < (BN * 8 + 255) / 256; i++) {
            int idx = tid + i * 256;
            if (BN * 8 % 256 == 0 || idx < BN * 8) {
                int r = idx >> 3, u = idx & 7;
                const __nv_bfloat16* src = Bb + (size_t)r * 2 * K +
                    ((u < 4) ? (k0 + u * 8) : (K + k0 + (u - 4) * 8));
                CP_ASYNC16(sb + swz((r << 7) | (u << 4)), (const char*)src);
            }
        }
    };

    float acc[MF][NF][4];
    #pragma unroll
    for (int i = 0; i < MF; i++)
        #pragma unroll
        for (int j = 0; j < NF; j++)
            #pragma unroll
            for (int e = 0; e < 4; e++) acc[i][j][e] = 0.0f;

    load_chunk(0, 0); CP_COMMIT();
    if (nch > 1) load_chunk(1, 1);
    CP_COMMIT();

    int a_mi = lane >> 3, a_r = lane & 7;
    int b_grp = lane >> 3, b_r = lane & 7;

    for (int c = 0; c < nch; c++) {
        CP_WAIT1();
        __syncthreads();
        if (c + 2 < nch) load_chunk(c + 2, (c + 2) % NSTG);
        CP_COMMIT();

        int s = c % NSTG;
        uint32_t sa = smb + s * STAGE;
        uint32_t sb = sa + A_BYTES;
        #pragma unroll
        for (int ksi = 0; ksi < 2; ksi++) {
            uint32_t afh[MF][4];
            #pragma unroll
            for (int mf = 0; mf < MF; mf++) {
                int row = wm * 32 + mf * 16 + ((a_mi & 1) << 3) + a_r;
                ldm_x4(afh[mf], sa + swz((row << 7) | ((ksi * 2 + (a_mi >> 1)) << 4)));
            }
            #pragma unroll
            for (int nfp = 0; nfp < NF / 2; nfp++) {
                uint32_t bfr[4];
                int row = wn * WN + (nfp * 2 + (b_grp >> 1)) * 8 + b_r;
                ldm_x4(bfr, sb + swz((row << 7) | ((ksi * 2 + (b_grp & 1)) << 4)));
                #pragma unroll
                for (int mf = 0; mf < MF; mf++) {
                    mma_bf16(acc[mf][nfp * 2 + 0], afh[mf], bfr);
                    mma_bf16(acc[mf][nfp * 2 + 1], afh[mf], bfr + 2);
                }
            }
            #pragma unroll
            for (int nfp = 0; nfp < NF / 2; nfp++) {
                uint32_t bfr[4];
                int row = wn * WN + (nfp * 2 + (b_grp >> 1)) * 8 + b_r;
                ldm_x4(bfr, sb + swz((row << 7) | ((4 + ksi * 2 + (b_grp & 1)) << 4)));
                #pragma unroll
                for (int mf = 0; mf < MF; mf++) {
                    mma_bf16(acc[mf][nfp * 2 + 0], afh[mf], bfr);
                    mma_bf16(acc[mf][nfp * 2 + 1], afh[mf], bfr + 2);
                }
            }
            uint32_t afl[MF][4];
            #pragma unroll
            for (int mf = 0; mf < MF; mf++) {
                int row = wm * 32 + mf * 16 + ((a_mi & 1) << 3) + a_r;
                ldm_x4(afl[mf], sa + swz((row << 7) | ((4 + ksi * 2 + (a_mi >> 1)) << 4)));
            }
            #pragma unroll
            for (int nfp = 0; nfp < NF / 2; nfp++) {
                uint32_t bfr[4];
                int row = wn * WN + (nfp * 2 + (b_grp >> 1)) * 8 + b_r;
                ldm_x4(bfr, sb + swz((row << 7) | ((ksi * 2 + (b_grp & 1)) << 4)));
                #pragma unroll
                for (int mf = 0; mf < MF; mf++) {
                    mma_bf16(acc[mf][nfp * 2 + 0], afl[mf], bfr);
                    mma_bf16(acc[mf][nfp * 2 + 1], afl[mf], bfr + 2);
                }
            }
        }
    }

    int cr = lane >> 2, cc2 = (lane & 3) << 1;
    #pragma unroll
    for (int mf = 0; mf < MF; mf++) {
        #pragma unroll
        for (int half = 0; half < 2; half++) {
            int gm = bm + wm * 32 + mf * 16 + cr + half * 8;
            #pragma unroll
            for (int nf = 0; nf < NF; nf++) {
                int gn = bn + wn * WN + nf * 8 + cc2;
                float v0 = acc[mf][nf][half * 2 + 0];
                float v1 = acc[mf][nf][half * 2 + 1];
                if (bias) { v0 += __ldg(&bias[gn]); v1 += __ldg(&bias[gn + 1]); }
                if (GELU) { v0 = gelu_f(v0); v1 = gelu_f(v1); }
                if (MODE == 1) {
                    __nv_bfloat162 hp, lp;
                    split2(v0, v1, hp, lp);
                    __nv_bfloat16* row = Cx2 + (size_t)gm * (2 * N);
                    *(__nv_bfloat162*)(row + gn) = hp;
                    *(__nv_bfloat162*)(row + N + gn) = lp;
                } else if (MODE == 2) {
                    int b = gm / NN, n = gm - b * NN;
                    int part = gn / CC, w = gn - part * CC;
                    int h = w >> 6, d = w & 63;
                    int tile = n >> 6, r = n & 63;
                    int bh = b * HH + h;
                    __nv_bfloat162 hp, lp;
                    split2(v0, v1, hp, lp);
                    size_t sbase = ((size_t)(bh * 4 + tile)) * 2 * 4096;
                    if (part == 0) {
                        *(__nv_bfloat162*)(qs + sbase + r * 64 + d) = hp;
                        *(__nv_bfloat162*)(qs + sbase + 4096 + r * 64 + d) = lp;
                    } else if (part == 1) {
                        *(__nv_bfloat162*)(ks_ + sbase + r * 64 + d) = hp;
                        *(__nv_bfloat162*)(ks_ + sbase + 4096 + r * 64 + d) = lp;
                    } else {
                        vt[sbase + d * 64 + r] = hp.x;
                        vt[sbase + (d + 1) * 64 + r] = hp.y;
                        vt[sbase + 4096 + d * 64 + r] = lp.x;
                        vt[sbase + 4096 + (d + 1) * 64 + r] = lp.y;
                    }
                } else {
                    if (RES) {
                        float2 rv = *(const float2*)(res + (size_t)gm * N + gn);
                        v0 += rv.x; v1 += rv.y;
                    }
                    *(float2*)(C + (size_t)gm * N + gn) = make_float2(v0, v1);
                }
            }
        }
    }
}

// ================= fully fused attention: QK + softmax + AV in one CTA =================
// one CTA per (qt, bh), 256 threads. smem: Q 16K | K 64K | V 64K | P 64K = 208KB.
// QK phase: warps = m-stripe(4) x k-half(2). AV phase: warps = m-stripe(4) x n-half(2).
__global__ void __launch_bounds__(256)
attn_fused(const __nv_bfloat16* __restrict__ Qs, const __nv_bfloat16* __restrict__ Ks,
           const __nv_bfloat16* __restrict__ Vt, __nv_bfloat16* __restrict__ Ox2) {
    extern __shared__ __align__(128) char smdyn[];
    uint32_t smb = smem_u32(smdyn);
    uint32_t smQ = smb, smK = smb + 16384, smV = smb + 81920, smP = smb + 147456;
    __shared__ float redmx[2][64], redsum[2][64];
    int qt = blockIdx.x, bh = blockIdx.y;
    int b = bh / HH, h = bh % HH;
    int tid = threadIdx.x, wid = tid >> 5, lane = tid & 31;
    int wm = wid & 3, g = wid >> 2;
    int a_mi = lane >> 3, a_r = lane & 7, b_grp = lane >> 3, b_r = lane & 7;

    // one bulk load: Q tile + all K tiles + all V tiles
    const char* Qb = (const char*)(Qs + ((size_t)(bh * 4 + qt)) * 2 * 4096);
    const char* Kb = (const char*)(Ks + ((size_t)(bh * 4)) * 2 * 4096);
    const char* Vb = (const char*)(Vt + ((size_t)(bh * 4)) * 2 * 4096);
    for (int c = tid; c < 1024; c += 256) {
        int slab = c >> 9, rem = c & 511, row = rem >> 3, unit = rem & 7;
        CP_ASYNC16(smQ + slab * 8192 + swz((row << 7) | (unit << 4)), Qb + (size_t)c * 16);
    }
    for (int c = tid; c < 4096; c += 256) {
        int tile = c >> 10, rem1 = c & 1023;
        int slab = rem1 >> 9, rem = rem1 & 511, row = rem >> 3, unit = rem & 7;
        uint32_t off = tile * 16384 + slab * 8192 + swz((row << 7) | (unit << 4));
        CP_ASYNC16(smK + off, Kb + (size_t)c * 16);
        CP_ASYNC16(smV + off, Vb + (size_t)c * 16);
    }
    CP_COMMIT(); CP_WAIT0();
    __syncthreads();

    // ---- QK phase ----
    float acc[2][8][4];
    #pragma unroll
    for (int kti = 0; kti < 2; kti++)
        #pragma unroll
        for (int nf = 0; nf < 8; nf++)
            #pragma unroll
            for (int e = 0; e < 4; e++) acc[kti][nf][e] = 0.f;

    const int pa[3] = {0, 0, 1}, pb[3] = {0, 1, 0};
    #pragma unroll
    for (int kti = 0; kti < 2; kti++) {
        uint32_t smKt = smK + (g * 2 + kti) * 16384;
        #pragma unroll
        for (int p = 0; p < 3; p++) {
            #pragma unroll
            for (int ksi = 0; ksi < 4; ksi++) {
                uint32_t afr[4];
                int arow = wm * 16 + ((a_mi & 1) << 3) + a_r;
                ldm_x4(afr, smQ + pa[p] * 8192 + swz((arow << 7) | ((ksi * 2 + (a_mi >> 1)) << 4)));
                #pragma unroll
                for (int nfp = 0; nfp < 4; nfp++) {
                    uint32_t bfr[4];
                    int brow = (nfp * 2 + (b_grp >> 1)) * 8 + b_r;
                    ldm_x4(bfr, smKt + pb[p] * 8192 + swz((brow << 7) | ((ksi * 2 + (b_grp & 1)) << 4)));
                    mma_bf16(acc[kti][nfp * 2 + 0], afr, bfr);
                    mma_bf16(acc[kti][nfp * 2 + 1], afr, bfr + 2);
                }
            }
        }
    }

    int cr = lane >> 2, cc2 = (lane & 3) << 1;
    int r0 = wm * 16 + cr, r1 = r0 + 8;
    #pragma unroll
    for (int kti = 0; kti < 2; kti++)
        #pragma unroll
        for (int nf = 0; nf < 8; nf++)
            #pragma unroll
            for (int e = 0; e < 4; e++) {
                int k = (g * 2 + kti) * 64 + nf * 8 + cc2 + (e & 1);
                float s = acc[kti][nf][e] * 0.125f;
                acc[kti][nf][e] = (k < NN) ? s : -INFINITY;
            }
    float mx0 = -INFINITY, mx1 = -INFINITY;
    #pragma unroll
    for (int kti = 0; kti < 2; kti++)
        #pragma unroll
        for (int nf = 0; nf < 8; nf++) {
            mx0 = fmaxf(mx0, fmaxf(acc[kti][nf][0], acc[kti][nf][1]));
            mx1 = fmaxf(mx1, fmaxf(acc[kti][nf][2], acc[kti][nf][3]));
        }
    #pragma unroll
    for (int o = 1; o <= 2; o <<= 1) {
        mx0 = fmaxf(mx0, __shfl_xor_sync(0xffffffff, mx0, o));
        mx1 = fmaxf(mx1, __shfl_xor_sync(0xffffffff, mx1, o));
    }
    if ((lane & 3) == 0) { redmx[g][r0] = mx0; redmx[g][r1] = mx1; }
    __syncthreads();
    mx0 = fmaxf(mx0, redmx[1 ^ g][r0]);
    mx1 = fmaxf(mx1, redmx[1 ^ g][r1]);
    float s0 = 0.f, s1 = 0.f;
    #pragma unroll
    for (int kti = 0; kti < 2; kti++)
        #pragma unroll
        for (int nf = 0; nf < 8; nf++) {
            float e0 = __expf(acc[kti][nf][0] - mx0);
            float e1 = __expf(acc[kti][nf][1] - mx0);
            float e2 = __expf(acc[kti][nf][2] - mx1);
            float e3 = __expf(acc[kti][nf][3] - mx1);
            acc[kti][nf][0] = e0; acc[kti][nf][1] = e1;
            acc[kti][nf][2] = e2; acc[kti][nf][3] = e3;
            s0 += e0 + e1; s1 += e2 + e3;
        }
    #pragma unroll
    for (int o = 1; o <= 2; o <<= 1) {
        s0 += __shfl_xor_sync(0xffffffff, s0, o);
        s1 += __shfl_xor_sync(0xffffffff, s1, o);
    }
    if ((lane & 3) == 0) { redsum[g][r0] = s0; redsum[g][r1] = s1; }
    __syncthreads();
    s0 += redsum[1 ^ g][r0];
    s1 += redsum[1 ^ g][r1];
    float inv0 = 1.0f / s0, inv1 = 1.0f / s1;

    // write P slabs to smem (layout identical to the old global P tiles)
    #pragma unroll
    for (int kti = 0; kti < 2; kti++) {
        int kt = g * 2 + kti;
        uint32_t smPt = smP + kt * 16384;
        #pragma unroll
        for (int nf = 0; nf < 8; nf++) {
            int col = nf * 8 + cc2;
            __nv_bfloat162 hp, lp;
            split2(acc[kti][nf][0] * inv0, acc[kti][nf][1] * inv0, hp, lp);
            uint32_t off0 = swz((r0 << 7) | (col << 1));
            *(__nv_bfloat162*)(smdyn + (smPt - smb) + off0) = hp;
            *(__nv_bfloat162*)(smdyn + (smPt - smb) + 8192 + off0) = lp;
            split2(acc[kti][nf][2] * inv1, acc[kti][nf][3] * inv1, hp, lp);
            uint32_t off1 = swz((r1 << 7) | (col << 1));
            *(__nv_bfloat162*)(smdyn + (smPt - smb) + off1) = hp;
            *(__nv_bfloat162*)(smdyn + (smPt - smb) + 8192 + off1) = lp;
        }
    }
    __syncthreads();

    // ---- AV phase: warps = m-stripe(4) x n-half(2) ----
    int wh = g;
    float acc2[4][4];
    #pragma unroll
    for (int i = 0; i < 4; i++)
        #pragma unroll
        for (int e = 0; e < 4; e++) acc2[i][e] = 0.f;
    #pragma unroll
    for (int kt = 0; kt < 4; kt++) {
        uint32_t smPt = smP + kt * 16384;
        uint32_t smVt = smV + kt * 16384;
        #pragma unroll
        for (int p = 0; p < 3; p++) {
            #pragma unroll
            for (int ksi = 0; ksi < 4; ksi++) {
                uint32_t afr[4];
                int arow = wm * 16 + ((a_mi & 1) << 3) + a_r;
                ldm_x4(afr, smPt + pa[p] * 8192 + swz((arow << 7) | ((ksi * 2 + (a_mi >> 1)) << 4)));
                #pragma unroll
                for (int nfp = 0; nfp < 2; nfp++) {
                    uint32_t bfr[4];
                    int brow = wh * 32 + (nfp * 2 + (b_grp >> 1)) * 8 + b_r;
                    ldm_x4(bfr, smVt + pb[p] * 8192 + swz((brow << 7) | ((ksi * 2 + (b_grp & 1)) << 4)));
                    mma_bf16(acc2[nfp * 2 + 0], afr, bfr);
                    mma_bf16(acc2[nfp * 2 + 1], afr, bfr + 2);
                }
            }
        }
    }
    #pragma unroll
    for (int nf = 0; nf < 4; nf++) {
        #pragma unroll
        for (int half = 0; half < 2; half++) {
            int q = qt * 64 + wm * 16 + cr + half * 8;
            if (q < NN) {
                int m = b * NN + q;
                int col = h * HD + wh * 32 + nf * 8 + cc2;
                __nv_bfloat162 hp, lp;
                split2(acc2[nf][half * 2 + 0], acc2[nf][half * 2 + 1], hp, lp);
                __nv_bfloat16* row = Ox2 + (size_t)m * (2 * CC);
                *(__nv_bfloat162*)(row + col) = hp;
                *(__nv_bfloat162*)(row + CC + col) = lp;
            }
        }
    }
}

// ---------------- LayerNorm D=768 -> [hi|lo] ----------------
__global__ void ln768_x2(const float* __restrict__ x, const float* __restrict__ g,
                         const float* __restrict__ b, __nv_bfloat16* __restrict__ out) {
    int row = blockIdx.x;
    const float* p = x + (size_t)row * CC;
    int tid = threadIdx.x;
    float v0 = p[tid], v1 = p[tid + 256], v2 = p[tid + 512];
    float s = v0 + v1 + v2;
    float sq = v0 * v0 + v1 * v1 + v2 * v2;
    __shared__ float rs[256], rq[256];
    rs[tid] = s; rq[tid] = sq; __syncthreads();
    for (int st = 128; st > 0; st >>= 1) {
        if (tid < st) { rs[tid] += rs[tid + st]; rq[tid] += rq[tid + st]; }
        __syncthreads();
    }
    float mean = rs[0] * (1.0f / CC);
    float var  = rq[0] * (1.0f / CC) - mean * mean;
    float inv = rsqrtf(var + 1e-5f);
    __nv_bfloat16* o = out + (size_t)row * (2 * CC);
    #pragma unroll
    for (int j = 0; j < 3; j++) {
        int c = tid + j * 256;
        float y = (p[c] - mean) * inv * g[c] + b[c];
        __nv_bfloat16 hi = __float2bfloat16(y);
        o[c] = hi;
        o[CC + c] = __float2bfloat16(y - __bfloat162float(hi));
    }
}

// ---------------- LayerNorm D=32 ----------------
__global__ void ln32_kernel(const float* __restrict__ x, const float* __restrict__ g,
                            const float* __restrict__ b, float* __restrict__ out) {
    int row = blockIdx.x * 8 + threadIdx.x / 32;
    int lane = threadIdx.x & 31;
    float v = x[(size_t)row * OUTC + lane];
    float s = v, sq = v * v;
    #pragma unroll
    for (int o = 16; o > 0; o >>= 1) {
        s  += __shfl_xor_sync(0xffffffff, s, o);
        sq += __shfl_xor_sync(0xffffffff, sq, o);
    }
    float mean = s * (1.0f / OUTC);
    float var  = sq * (1.0f / OUTC) - mean * mean;
    float inv = rsqrtf(var + 1e-5f);
    out[(size_t)row * OUTC + lane] = (v - mean) * inv * g[lane] + b[lane];
}

// ---------------- fp32 SIMT GEMM (small channel GEMMs) ----------------
template<int BM, int BN, int BK, int TM, int TN, bool GELU, bool RES>
__global__ void gemm_nt(const float* __restrict__ A, const float* __restrict__ Bw,
                        const float* __restrict__ bias, const float* __restrict__ res,
                        float* __restrict__ C, int M, int N, int K) {
    constexpr int THREADS = (BM / TM) * (BN / TN);
    __shared__ float As[BK][BM];
    __shared__ float Bs[BK][BN];
    int tid = threadIdx.x;
    int bm = blockIdx.y * BM, bn = blockIdx.x * BN;
    int tx = tid % (BN / TN), ty = tid / (BN / TN);
    float acc[TM][TN];
    #pragma unroll
    for (int i = 0; i < TM; i++)
        #pragma unroll
        for (int j = 0; j < TN; j++) acc[i][j] = 0.0f;
    constexpr int A4 = BM * BK / 4;
    constexpr int B4 = BN * BK / 4;
    for (int k0 = 0; k0 < K; k0 += BK) {
        #pragma unroll
        for (int i = tid; i < A4; i += THREADS) {
            int row = i / (BK / 4);
            int kk  = (i % (BK / 4)) * 4;
            float4 v = make_float4(0.f, 0.f, 0.f, 0.f);
            if (k0 + kk < K) v = *(const float4*)(A + (size_t)(bm + row) * K + k0 + kk);
            As[kk + 0][row] = v.x; As[kk + 1][row] = v.y;
            As[kk + 2][row] = v.z; As[kk + 3][row] = v.w;
        }
        #pragma unroll
        for (int i = tid; i < B4; i += THREADS) {
            int row = i / (BK / 4);
            int kk  = (i % (BK / 4)) * 4;
            float4 v = make_float4(0.f, 0.f, 0.f, 0.f);
            if (bn + row < N && k0 + kk < K)
                v = *(const float4*)(Bw + (size_t)(bn + row) * K + k0 + kk);
            Bs[kk + 0][row] = v.x; Bs[kk + 1][row] = v.y;
            Bs[kk + 2][row] = v.z; Bs[kk + 3][row] = v.w;
        }
        __syncthreads();
        #pragma unroll
        for (int kk = 0; kk < BK; kk++) {
            float a[TM], bv[TN];
            #pragma unroll
            for (int i = 0; i < TM; i++) a[i] = As[kk][ty * TM + i];
            #pragma unroll
            for (int j = 0; j < TN; j++) bv[j] = Bs[kk][tx * TN + j];
            #pragma unroll
            for (int i = 0; i < TM; i++)
                #pragma unroll
                for (int j = 0; j < TN; j++) acc[i][j] += a[i] * bv[j];
        }
        __syncthreads();
    }
    #pragma unroll
    for (int i = 0; i < TM; i++) {
        int gm = bm + ty * TM + i;
        #pragma unroll
        for (int j = 0; j < TN; j++) {
            int gn = bn + tx * TN + j;
            if (gn < N) {
                float v = acc[i][j];
                if (bias) v += bias[gn];
                if (GELU) v = gelu_f(v);
                if (RES) v += res[(size_t)gm * N + gn];
                C[(size_t)gm * N + gn] = v;
            }
        }
    }
}

// ---------------- t[b,c,s] = ln3[b, 1+s, c] ----------------
__global__ void make_t_kernel(const float* __restrict__ ln3, float* __restrict__ t) {
    int idx = blockIdx.x * 256 + threadIdx.x;
    if (idx >= BB * OUTC * CNN) return;
    int s = idx % CNN;
    int c = (idx / CNN) % OUTC;
    int b = idx / (CNN * OUTC);
    t[idx] = ln3[((size_t)(b * NN + 1 + s)) * OUTC + c];
}

// ---------------- tiny channel attention ----------------
__global__ void chattn_kernel(const float* __restrict__ cqkv, float* __restrict__ co) {
    int b = blockIdx.x / CHH, h = blockIdx.x % CHH;
    int tid = threadIdx.x;
    __shared__ float Q[OUTC][CHD], Kk[OUTC][CHD], V[OUTC][CHD], S[OUTC][OUTC + 1];
    const float* base = cqkv + (size_t)b * OUTC * (3 * CNN);
    for (int i = tid; i < OUTC * CHD; i += 256) {
        int r = i / CHD, d = i % CHD;
        Q[r][d]  = base[r * (3 * CNN) + h * CHD + d];
        Kk[r][d] = base[r * (3 * CNN) + CNN + h * CHD + d];
        V[r][d]  = base[r * (3 * CNN) + 2 * CNN + h * CHD + d];
    }
    __syncthreads();
    const float sc = rsqrtf((float)CHD);
    for (int i = tid; i < OUTC * OUTC; i += 256) {
        int qi = i / OUTC, kj = i % OUTC;
        float s = 0.0f;
        #pragma unroll
        for (int d = 0; d < CHD; d++) s += Q[qi][d] * Kk[kj][d];
        S[qi][kj] = s * sc;
    }
    __syncthreads();
    if (tid < OUTC) {
        float mx = -INFINITY;
        #pragma unroll
        for (int j = 0; j < OUTC; j++) mx = fmaxf(mx, S[tid][j]);
        float sum = 0.0f;
        #pragma unroll
        for (int j = 0; j < OUTC; j++) { float e = __expf(S[tid][j] - mx); S[tid][j] = e; sum += e; }
        float inv = 1.0f / sum;
        #pragma unroll
        for (int j = 0; j < OUTC; j++) S[tid][j] *= inv;
    }
    __syncthreads();
    for (int i = tid; i < OUTC * CHD; i += 256) {
        int qi = i / CHD, d = i % CHD;
        float s = 0.0f;
        #pragma unroll
        for (int kk = 0; kk < OUTC; kk++) s += S[qi][kk] * V[kk][d];
        co[((size_t)(b * OUTC + qi)) * CNN + h * CHD + d] = s;
    }
}

// ---------------- x32 += concat([ln3 cls, co2^T]) ----------------
__global__ void concat_add_kernel(const float* __restrict__ ln3, const float* __restrict__ co2,
                                  float* __restrict__ x32) {
    int idx = blockIdx.x * 256 + threadIdx.x;
    if (idx >= MROWS * OUTC) return;
    int c = idx % OUTC;
    int n = (idx / OUTC) % NN;
    int b = idx / (OUTC * NN);
    float add;
    if (n == 0) add = ln3[((size_t)b * NN) * OUTC + c];
    else        add = co2[((size_t)(b * OUTC + c)) * CNN + (n - 1)];
    x32[idx] += add;
}

// ---------------- launch ----------------
static inline int cdiv(long long a, int b) { return (int)((a + b - 1) / b); }

extern "C" void kernel_launch(void* const* d_in, const int* in_sizes, int n_in,
                              void* d_out, int out_size) {
    const float* x      = (const float*)d_in[0];
    const float* g1     = (const float*)d_in[1];
    const float* b1     = (const float*)d_in[2];
    const float* w_qkv  = (const float*)d_in[3];
    const float* w_proj = (const float*)d_in[4];
    const float* b_proj = (const float*)d_in[5];
    const float* g2     = (const float*)d_in[6];
    const float* b2     = (const float*)d_in[7];
    const float* w_fc1  = (const float*)d_in[8];
    const float* b_fc1  = (const float*)d_in[9];
    const float* w_fc2  = (const float*)d_in[10];
    const float* b_fc2  = (const float*)d_in[11];
    const float* g3     = (const float*)d_in[12];
    const float* b3     = (const float*)d_in[13];
    const float* w_cqkv = (const float*)d_in[14];
    const float* w_cproj= (const float*)d_in[15];
    const float* b_cproj= (const float*)d_in[16];
    const float* g4     = (const float*)d_in[17];
    const float* b4     = (const float*)d_in[18];
    const float* w_cfc1 = (const float*)d_in[19];
    const float* b_cfc1 = (const float*)d_in[20];
    const float* w_cfc2 = (const float*)d_in[21];
    const float* b_cfc2 = (const float*)d_in[22];
    float* out = (float*)d_out;

    float *p_x, *p_x32, *p_ln32, *p_t, *p_cqkv, *p_co, *p_co2, *p_cmlp;
    __nv_bfloat16 *p_abf, *p_abf2, *p_wbf, *p_qs, *p_ks, *p_vt;
    cudaGetSymbolAddress((void**)&p_x,    g_x);
    cudaGetSymbolAddress((void**)&p_x32,  g_x32);
    cudaGetSymbolAddress((void**)&p_ln32, g_ln32);
    cudaGetSymbolAddress((void**)&p_t,    g_t);
    cudaGetSymbolAddress((void**)&p_cqkv, g_cqkv);
    cudaGetSymbolAddress((void**)&p_co,   g_co);
    cudaGetSymbolAddress((void**)&p_co2,  g_co2);
    cudaGetSymbolAddress((void**)&p_cmlp, g_cmlp);
    cudaGetSymbolAddress((void**)&p_abf,  g_abf);
    cudaGetSymbolAddress((void**)&p_abf2, g_abf2);
    cudaGetSymbolAddress((void**)&p_wbf,  g_wbf);
    cudaGetSymbolAddress((void**)&p_qs,   g_qs);
    cudaGetSymbolAddress((void**)&p_ks,   g_ks);
    cudaGetSymbolAddress((void**)&p_vt,   g_vt);

    const int SM128 = 3 * (128 * 128 + 128 * 128) + 1024;
    const int SM32  = 3 * (128 * 128 + 32 * 128) + 1024;
    const int SMATT = 16384 + 65536 + 65536 + 65536;   // 212992
    cudaFuncSetAttribute(gemm_mma<128, false, false, 2>, cudaFuncAttributeMaxDynamicSharedMemorySize, SM128);
    cudaFuncSetAttribute(gemm_mma<128, false, true,  0>, cudaFuncAttributeMaxDynamicSharedMemorySize, SM128);
    cudaFuncSetAttribute(gemm_mma<128, true,  false, 1>, cudaFuncAttributeMaxDynamicSharedMemorySize, SM128);
    cudaFuncSetAttribute(gemm_mma<32,  false, false, 0>, cudaFuncAttributeMaxDynamicSharedMemorySize, SM32);
    cudaFuncSetAttribute(gemm_mma<32,  false, true,  0>, cudaFuncAttributeMaxDynamicSharedMemorySize, SM32);
    cudaFuncSetAttribute(attn_fused, cudaFuncAttributeMaxDynamicSharedMemorySize, SMATT);

    const int M = MROWS;
    const int MB = M / 128;

    // 1. LN1 -> [hi|lo]
    ln768_x2<<<M, 256>>>(x, g1, b1, p_abf);
    // 2. qkv GEMM, epilogue writes Q/K/V slabs directly
    conv_x2<<<cdiv((long long)3 * CC * CC / 4, 256), 256>>>(w_qkv, p_wbf, 3 * CC, CC);
    gemm_mma<128, false, false, 2><<<dim3(18, MB), 256, SM128>>>(
        p_abf, p_wbf, nullptr, nullptr, nullptr, nullptr, p_qs, p_ks, p_vt, M, 3 * CC, CC);
    // 3. fully fused attention
    attn_fused<<<dim3(4, NBH), 256, SMATT>>>(p_qs, p_ks, p_vt, p_abf);
    // 4. x = x_in + O @ w_proj^T + b_proj
    conv_x2<<<cdiv((long long)CC * CC / 4, 256), 256>>>(w_proj, p_wbf, CC, CC);
    gemm_mma<128, false, true, 0><<<dim3(6, MB), 256, SM128>>>(
        p_abf, p_wbf, b_proj, x, p_x, nullptr, nullptr, nullptr, nullptr, M, CC, CC);
    // 5. LN2 -> [hi|lo]
    ln768_x2<<<M, 256>>>(p_x, g2, b2, p_abf);
    // 6. hidden = gelu(...) -> [hi|lo]
    conv_x2<<<cdiv((long long)MLPH * CC / 4, 256), 256>>>(w_fc1, p_wbf, MLPH, CC);
    gemm_mma<128, true, false, 1><<<dim3(24, MB), 256, SM128>>>(
        p_abf, p_wbf, b_fc1, nullptr, nullptr, p_abf2, nullptr, nullptr, nullptr, M, MLPH, CC);
    // 7. x32 = hidden @ w_fc2^T + b_fc2
    conv_x2<<<cdiv((long long)OUTC * MLPH / 4, 256), 256>>>(w_fc2, p_wbf, OUTC, MLPH);
    gemm_mma<32, false, false, 0><<<dim3(1, MB), 256, SM32>>>(
        p_abf2, p_wbf, b_fc2, nullptr, p_x32, nullptr, nullptr, nullptr, nullptr, M, OUTC, MLPH);
    // 8. LN3
    ln32_kernel<<<M / 8, 256>>>(p_x32, g3, b3, p_ln32);
    // 9. channel branch
    make_t_kernel<<<(BB * OUTC * CNN + 255) / 256, 256>>>(p_ln32, p_t);
    gemm_nt<128, 128, 16, 8, 8, false, false><<<dim3(5, CMROWS / 128), 256>>>(p_t, w_cqkv, nullptr, nullptr, p_cqkv, CMROWS, 3 * CNN, CNN);
    chattn_kernel<<<BB * CHH, 256>>>(p_cqkv, p_co);
    gemm_nt<128, 128, 16, 8, 8, false, false><<<dim3(2, CMROWS / 128), 256>>>(p_co, w_cproj, b_cproj, nullptr, p_co2, CMROWS, CNN, CNN);
    concat_add_kernel<<<(M * OUTC + 255) / 256, 256>>>(p_ln32, p_co2, p_x32);
    // 10. LN4 + channel MLP
    ln32_kernel<<<M / 8, 256>>>(p_x32, g4, b4, p_ln32);
    gemm_nt<128, 128, 16, 8, 8, true, false><<<dim3(1, MB), 256>>>(p_ln32, w_cfc1, b_cfc1, nullptr, p_cmlp, M, CMLPH, OUTC);
    conv_x2<<<cdiv((long long)M * CMLPH / 4, 256), 256>>>(p_cmlp, p_abf, M, CMLPH);
    conv_x2<<<cdiv((long long)OUTC * CMLPH / 4, 256), 256>>>(w_cfc2, p_wbf, OUTC, CMLPH);
    gemm_mma<32, false, true, 0><<<dim3(1, MB), 256, SM32>>>(
        p_abf, p_wbf, b_cfc2, p_x32, out, nullptr, nullptr, nullptr, nullptr, M, OUTC, CMLPH);
}